// round 2
// baseline (speedup 1.0000x reference)
#include <cuda_runtime.h>

// Problem constants
#define T_TOK 4096
#define D_DIM 1024
#define H_DIM 1024
#define E_NUM 16
#define K_TOP 2
#define CAPCT 1024

// ---------------- scratch (device globals; no allocations allowed) ----------
__device__ int   g_count[E_NUM];
__device__ int   g_slot_tok[E_NUM * CAPCT];          // slot -> source token
__device__ int   g_t_slot[T_TOK * K_TOP];            // token,k -> slot (e*CAP+pos) or -1
__device__ float g_t_score[T_TOK * K_TOP];           // token,k -> gate score
__device__ float g_h[(size_t)E_NUM * CAPCT * H_DIM]; // 64 MB
__device__ float g_y[(size_t)E_NUM * CAPCT * D_DIM]; // 64 MB

// ---------------- init: zero per-expert counters ----------------------------
__global__ void init_kernel() {
    if (threadIdx.x < E_NUM) g_count[threadIdx.x] = 0;
}

// ---------------- gate: one warp per token ----------------------------------
__global__ void gate_kernel(const float* __restrict__ x,
                            const float* __restrict__ Wg,
                            const float* __restrict__ bg) {
    int warp = (blockIdx.x * blockDim.x + threadIdx.x) >> 5;
    int lane = threadIdx.x & 31;
    if (warp >= T_TOK) return;
    const float* xr = x + (size_t)warp * D_DIM;

    float acc[E_NUM];
#pragma unroll
    for (int e = 0; e < E_NUM; e++) acc[e] = 0.f;

    for (int d = lane; d < D_DIM; d += 32) {
        float xv = __ldg(xr + d);
        const float4* w = reinterpret_cast<const float4*>(Wg + (size_t)d * E_NUM);
#pragma unroll
        for (int q = 0; q < 4; q++) {
            float4 wv = __ldg(w + q);
            acc[q * 4 + 0] += xv * wv.x;
            acc[q * 4 + 1] += xv * wv.y;
            acc[q * 4 + 2] += xv * wv.z;
            acc[q * 4 + 3] += xv * wv.w;
        }
    }
#pragma unroll
    for (int e = 0; e < E_NUM; e++) {
#pragma unroll
        for (int off = 16; off > 0; off >>= 1)
            acc[e] += __shfl_xor_sync(0xffffffffu, acc[e], off);
    }

    if (lane == 0) {
        float v[E_NUM];
#pragma unroll
        for (int e = 0; e < E_NUM; e++) v[e] = acc[e] + bg[e];
        // top-1 (ties -> lower index, matching jax.lax.top_k)
        int i0 = 0; float v0 = v[0];
#pragma unroll
        for (int e = 1; e < E_NUM; e++) if (v[e] > v0) { v0 = v[e]; i0 = e; }
        // top-2
        int i1 = -1; float v1 = -3.4e38f;
#pragma unroll
        for (int e = 0; e < E_NUM; e++)
            if (e != i0 && v[e] > v1) { v1 = v[e]; i1 = e; }
        // softmax over the two kept logits
        float e1 = expf(v1 - v0);
        float s0 = 1.f / (1.f + e1);
        float s1 = e1 / (1.f + e1);

        int p0 = atomicAdd(&g_count[i0], 1);
        int p1 = atomicAdd(&g_count[i1], 1);
        if (p0 < CAPCT) {
            g_slot_tok[i0 * CAPCT + p0] = warp;
            g_t_slot[warp * 2 + 0] = i0 * CAPCT + p0;
        } else {
            g_t_slot[warp * 2 + 0] = -1;
        }
        if (p1 < CAPCT) {
            g_slot_tok[i1 * CAPCT + p1] = warp;
            g_t_slot[warp * 2 + 1] = i1 * CAPCT + p1;
        } else {
            g_t_slot[warp * 2 + 1] = -1;
        }
        g_t_score[warp * 2 + 0] = s0;
        g_t_score[warp * 2 + 1] = s1;
    }
}

// ---------------- grouped GEMM --------------------------------------------
// LAYER 0: C(g_h) = relu( gather(x)[rows<cnt] @ W1[e] + b1[e] ),  Kd=D, Nd=H
// LAYER 1: C(g_y) = g_h[rows<cnt] @ W2[e] + b2[e],                Kd=H, Nd=D
template <int LAYER>
__global__ __launch_bounds__(256, 2)
void grouped_gemm(const float* __restrict__ X,   // only used by LAYER 0
                  const float* __restrict__ W,   // [E, Kd, Nd]
                  const float* __restrict__ bias,// [E, Nd]
                  int Kd, int Nd) {
    const int e = blockIdx.z;
    int cnt = g_count[e];
    if (cnt > CAPCT) cnt = CAPCT;
    const int m0 = blockIdx.y * 128;
    if (m0 >= cnt) return;
    const int n0 = blockIdx.x * 128;

    __shared__ float As[16][128];
    __shared__ float Bs[16][128];

    const int tid = threadIdx.x;
    const int tx = tid & 15;        // output col group
    const int ty = tid >> 4;        // output row group

    // --- A-load mapping: thread loads row (tid>>1), cols (tid&1)*8 .. +7
    const int arow = tid >> 1;
    const int acol = (tid & 1) * 8;
    const float* aptr;
    if (LAYER == 0) {
        int tok = g_slot_tok[e * CAPCT + m0 + arow];   // rows >= cnt may read stale data
        tok = min(max(tok, 0), T_TOK - 1);             // clamp: safe address, result unused
        aptr = X + (size_t)tok * D_DIM + acol;
    } else {
        aptr = g_h + ((size_t)e * CAPCT + m0 + arow) * H_DIM + acol;
    }

    // --- B-load mapping: two float4 per thread
    const int brow0 = tid >> 5;          // 0..7
    const int bcol  = (tid & 31) * 4;    // 0..124
    const float* wbase = W + (size_t)e * Kd * Nd + n0;

    float accv[8][8];
#pragma unroll
    for (int i = 0; i < 8; i++)
#pragma unroll
        for (int j = 0; j < 8; j++) accv[i][j] = 0.f;

    const int nkt = Kd >> 4;
    for (int kt = 0; kt < nkt; kt++) {
        const int k0 = kt << 4;
        // prefetch globals into registers
        float4 a0 = *reinterpret_cast<const float4*>(aptr + k0);
        float4 a1 = *reinterpret_cast<const float4*>(aptr + k0 + 4);
        float4 b0 = *reinterpret_cast<const float4*>(wbase + (size_t)(k0 + brow0) * Nd + bcol);
        float4 b1 = *reinterpret_cast<const float4*>(wbase + (size_t)(k0 + brow0 + 8) * Nd + bcol);

        __syncthreads();   // previous tile fully consumed
        As[acol + 0][arow] = a0.x;
        As[acol + 1][arow] = a0.y;
        As[acol + 2][arow] = a0.z;
        As[acol + 3][arow] = a0.w;
        As[acol + 4][arow] = a1.x;
        As[acol + 5][arow] = a1.y;
        As[acol + 6][arow] = a1.z;
        As[acol + 7][arow] = a1.w;
        *reinterpret_cast<float4*>(&Bs[brow0][bcol])     = b0;
        *reinterpret_cast<float4*>(&Bs[brow0 + 8][bcol]) = b1;
        __syncthreads();

#pragma unroll
        for (int kk = 0; kk < 16; kk++) {
            float ar[8], br[8];
            *reinterpret_cast<float4*>(ar)     = *reinterpret_cast<const float4*>(&As[kk][ty * 8]);
            *reinterpret_cast<float4*>(ar + 4) = *reinterpret_cast<const float4*>(&As[kk][ty * 8 + 4]);
            *reinterpret_cast<float4*>(br)     = *reinterpret_cast<const float4*>(&Bs[kk][tx * 8]);
            *reinterpret_cast<float4*>(br + 4) = *reinterpret_cast<const float4*>(&Bs[kk][tx * 8 + 4]);
#pragma unroll
            for (int i = 0; i < 8; i++)
#pragma unroll
                for (int j = 0; j < 8; j++)
                    accv[i][j] += ar[i] * br[j];
        }
    }

    // epilogue
    float bv[8];
    const float* brow = bias + (size_t)e * Nd + n0 + tx * 8;
#pragma unroll
    for (int j = 0; j < 8; j++) bv[j] = brow[j];

    float* cbase = (LAYER == 0) ? g_h : g_y;
#pragma unroll
    for (int i = 0; i < 8; i++) {
        int m = m0 + ty * 8 + i;
        if (m >= cnt) continue;
        float* crow = cbase + ((size_t)e * CAPCT + m) * Nd + n0 + tx * 8;
        float r[8];
#pragma unroll
        for (int j = 0; j < 8; j++) {
            float t = accv[i][j] + bv[j];
            if (LAYER == 0) t = t > 0.f ? t : 0.f;
            r[j] = t;
        }
        *reinterpret_cast<float4*>(crow)     = make_float4(r[0], r[1], r[2], r[3]);
        *reinterpret_cast<float4*>(crow + 4) = make_float4(r[4], r[5], r[6], r[7]);
    }
}

// ---------------- combine: out[t] = s0*y[slot0] + s1*y[slot1] ----------------
__global__ void combine_kernel(float* __restrict__ out) {
    const int t = blockIdx.x;
    const int d4 = threadIdx.x;           // 256 threads, D/4 = 256
    const int s0 = g_t_slot[t * 2 + 0];
    const int s1 = g_t_slot[t * 2 + 1];
    const float c0 = g_t_score[t * 2 + 0];
    const float c1 = g_t_score[t * 2 + 1];

    float4 r = make_float4(0.f, 0.f, 0.f, 0.f);
    if (s0 >= 0) {
        float4 a = *(reinterpret_cast<const float4*>(g_y + (size_t)s0 * D_DIM) + d4);
        r.x += c0 * a.x; r.y += c0 * a.y; r.z += c0 * a.z; r.w += c0 * a.w;
    }
    if (s1 >= 0) {
        float4 a = *(reinterpret_cast<const float4*>(g_y + (size_t)s1 * D_DIM) + d4);
        r.x += c1 * a.x; r.y += c1 * a.y; r.z += c1 * a.z; r.w += c1 * a.w;
    }
    *(reinterpret_cast<float4*>(out + (size_t)t * D_DIM) + d4) = r;
}

// ---------------- launch -----------------------------------------------------
extern "C" void kernel_launch(void* const* d_in, const int* in_sizes, int n_in,
                              void* d_out, int out_size) {
    const float* x  = (const float*)d_in[0];
    const float* Wg = (const float*)d_in[1];
    const float* bg = (const float*)d_in[2];
    const float* W1 = (const float*)d_in[3];
    const float* b1 = (const float*)d_in[4];
    const float* W2 = (const float*)d_in[5];
    const float* b2 = (const float*)d_in[6];
    float* out = (float*)d_out;

    init_kernel<<<1, 32>>>();
    gate_kernel<<<T_TOK / 4, 128>>>(x, Wg, bg);   // 4 warps (tokens) per block

    dim3 gemm_grid(H_DIM / 128, CAPCT / 128, E_NUM);
    grouped_gemm<0><<<gemm_grid, 256>>>(x, W1, b1, D_DIM, H_DIM);

    dim3 gemm_grid2(D_DIM / 128, CAPCT / 128, E_NUM);
    grouped_gemm<1><<<gemm_grid2, 256>>>(nullptr, W2, b2, H_DIM, D_DIM);

    combine_kernel<<<T_TOK, 256>>>(out);
}

// round 5
// speedup vs baseline: 1.5204x; 1.5204x over previous
#include <cuda_runtime.h>
#include <cuda_bf16.h>
#include <cstdint>

// Problem constants
#define T_TOK 4096
#define D_DIM 1024
#define H_DIM 1024
#define E_NUM 16
#define K_TOP 2
#define CAPCT 1024

// GEMM tiling
#define BM 128
#define BN 128
#define KC 64                 // K elems per chunk (bf16 tile rows are 64*2=128 bytes)
#define NCHUNK (D_DIM / KC)   // 16

// ---------------- scratch (device globals; no allocations allowed) ----------
__device__ int   g_count[E_NUM];
__device__ int   g_slot_tok[E_NUM * CAPCT];
__device__ int   g_t_slot[T_TOK * K_TOP];
__device__ float g_t_score[T_TOK * K_TOP];
__device__ float g_h[(size_t)E_NUM * CAPCT * H_DIM]; // 64 MB
__device__ float g_y[(size_t)E_NUM * CAPCT * D_DIM]; // 64 MB

// ---------------- helpers ----------------------------------------------------
__device__ __forceinline__ uint32_t smem_u32(const void* p) {
    uint32_t a;
    asm("{ .reg .u64 t; cvta.to.shared.u64 t, %1; cvt.u32.u64 %0, t; }" : "=r"(a) : "l"(p));
    return a;
}
#define STS64(a, v) asm volatile("st.shared.b64 [%0], %1;" :: "r"(a), "l"(v) : "memory")

#define LDSM4(r, a) \
    asm volatile("ldmatrix.sync.aligned.m8n8.x4.shared.b16 {%0,%1,%2,%3}, [%4];" \
        : "=r"((r)[0]), "=r"((r)[1]), "=r"((r)[2]), "=r"((r)[3]) : "r"(a))

#define MMA16816(c, a, b0, b1) \
    asm volatile("mma.sync.aligned.m16n8k16.row.col.f32.bf16.bf16.f32 " \
        "{%0,%1,%2,%3}, {%4,%5,%6,%7}, {%8,%9}, {%0,%1,%2,%3};" \
        : "+f"((c)[0]), "+f"((c)[1]), "+f"((c)[2]), "+f"((c)[3]) \
        : "r"((a)[0]), "r"((a)[1]), "r"((a)[2]), "r"((a)[3]), "r"(b0), "r"(b1))

// split fp32x4 -> 4 hi bf16 (packed u64) + 4 lo bf16 (packed u64)
__device__ __forceinline__ void split4(float4 v, uint64_t& hi, uint64_t& lo) {
    float f[4] = {v.x, v.y, v.z, v.w};
    uint32_t h01, h23, l01, l23;
    {
        __nv_bfloat16 h0 = __float2bfloat16(f[0]);
        __nv_bfloat16 h1 = __float2bfloat16(f[1]);
        __nv_bfloat16 l0 = __float2bfloat16(f[0] - __bfloat162float(h0));
        __nv_bfloat16 l1 = __float2bfloat16(f[1] - __bfloat162float(h1));
        h01 = (uint32_t)__bfloat16_as_ushort(h0) | ((uint32_t)__bfloat16_as_ushort(h1) << 16);
        l01 = (uint32_t)__bfloat16_as_ushort(l0) | ((uint32_t)__bfloat16_as_ushort(l1) << 16);
    }
    {
        __nv_bfloat16 h2 = __float2bfloat16(f[2]);
        __nv_bfloat16 h3 = __float2bfloat16(f[3]);
        __nv_bfloat16 l2 = __float2bfloat16(f[2] - __bfloat162float(h2));
        __nv_bfloat16 l3 = __float2bfloat16(f[3] - __bfloat162float(h3));
        h23 = (uint32_t)__bfloat16_as_ushort(h2) | ((uint32_t)__bfloat16_as_ushort(h3) << 16);
        l23 = (uint32_t)__bfloat16_as_ushort(l2) | ((uint32_t)__bfloat16_as_ushort(l3) << 16);
    }
    hi = (uint64_t)h01 | ((uint64_t)h23 << 32);
    lo = (uint64_t)l01 | ((uint64_t)l23 << 32);
}

// ---------------- init -------------------------------------------------------
__global__ void init_kernel() {
    if (threadIdx.x < E_NUM) g_count[threadIdx.x] = 0;
}

// ---------------- gate: one warp per token ----------------------------------
__global__ void gate_kernel(const float* __restrict__ x,
                            const float* __restrict__ Wg,
                            const float* __restrict__ bg) {
    int warp = (blockIdx.x * blockDim.x + threadIdx.x) >> 5;
    int lane = threadIdx.x & 31;
    if (warp >= T_TOK) return;
    const float* xr = x + (size_t)warp * D_DIM;

    float acc[E_NUM];
#pragma unroll
    for (int e = 0; e < E_NUM; e++) acc[e] = 0.f;

    for (int d = lane; d < D_DIM; d += 32) {
        float xv = __ldg(xr + d);
        const float4* w = reinterpret_cast<const float4*>(Wg + (size_t)d * E_NUM);
#pragma unroll
        for (int q = 0; q < 4; q++) {
            float4 wv = __ldg(w + q);
            acc[q * 4 + 0] += xv * wv.x;
            acc[q * 4 + 1] += xv * wv.y;
            acc[q * 4 + 2] += xv * wv.z;
            acc[q * 4 + 3] += xv * wv.w;
        }
    }
#pragma unroll
    for (int e = 0; e < E_NUM; e++) {
#pragma unroll
        for (int off = 16; off > 0; off >>= 1)
            acc[e] += __shfl_xor_sync(0xffffffffu, acc[e], off);
    }

    if (lane == 0) {
        float v[E_NUM];
#pragma unroll
        for (int e = 0; e < E_NUM; e++) v[e] = acc[e] + bg[e];
        int i0 = 0; float v0 = v[0];
#pragma unroll
        for (int e = 1; e < E_NUM; e++) if (v[e] > v0) { v0 = v[e]; i0 = e; }
        int i1 = -1; float v1 = -3.4e38f;
#pragma unroll
        for (int e = 0; e < E_NUM; e++)
            if (e != i0 && v[e] > v1) { v1 = v[e]; i1 = e; }
        float e1 = expf(v1 - v0);
        float s0 = 1.f / (1.f + e1);
        float s1 = e1 / (1.f + e1);

        int p0 = atomicAdd(&g_count[i0], 1);
        int p1 = atomicAdd(&g_count[i1], 1);
        if (p0 < CAPCT) {
            g_slot_tok[i0 * CAPCT + p0] = warp;
            g_t_slot[warp * 2 + 0] = i0 * CAPCT + p0;
        } else g_t_slot[warp * 2 + 0] = -1;
        if (p1 < CAPCT) {
            g_slot_tok[i1 * CAPCT + p1] = warp;
            g_t_slot[warp * 2 + 1] = i1 * CAPCT + p1;
        } else g_t_slot[warp * 2 + 1] = -1;
        g_t_score[warp * 2 + 0] = s0;
        g_t_score[warp * 2 + 1] = s1;
    }
}

// ---------------- HMMA grouped GEMM ------------------------------------------
// LAYER 0: g_h = relu( gather(x) @ W1[e] + b1[e] )
// LAYER 1: g_y = g_h @ W2[e] + b2[e]
// fp32 emulated via bf16 split: hi*hi + hi*lo + lo*hi, fp32 accumulators.
// smem per stage: A_hi[128][64] A_lo B_hi[128][64] B_lo (bf16, 128B rows, SW128 swizzle)
template <int LAYER>
__global__ __launch_bounds__(256, 1)
void gemm_tc(const float* __restrict__ X,     // LAYER 0 only
             const float* __restrict__ W,     // [E, 1024, 1024] (k-major rows)
             const float* __restrict__ bias)  // [E, 1024]
{
    const int e = blockIdx.z;
    int cnt = g_count[e];
    if (cnt > CAPCT) cnt = CAPCT;
    const int m0 = blockIdx.y * BM;
    if (m0 >= cnt) return;
    const int n0 = blockIdx.x * BN;

    extern __shared__ char smem[];
    const uint32_t buf = (smem_u32(smem) + 1023) & ~1023u;

    const int tid = threadIdx.x;
    const int lane = tid & 31;
    const int wid = tid >> 5;
    const int warp_m = wid >> 2;   // 0..1 -> 64-row slab
    const int warp_n = wid & 3;    // 0..3 -> 32-col slab

    // ---- producer mappings ----
    const int arow = tid >> 1;            // 0..127
    const int ahalf = (tid & 1) * 32;     // k sub-half
    const float* aptr;
    if (LAYER == 0) {
        int tok = g_slot_tok[e * CAPCT + m0 + arow];   // rows >= cnt: stale but finite
        tok = min(max(tok, 0), T_TOK - 1);
        aptr = X + (size_t)tok * D_DIM;
    } else {
        aptr = g_h + ((size_t)e * CAPCT + m0 + arow) * H_DIM;
    }
    const uint32_t a_sts = (uint32_t)arow * 128u;
    const uint32_t a_xm = (uint32_t)(arow & 7) * 16u;

    const int bn = tid & 127;             // output column within tile
    const int bkh = (tid >> 7) * 32;      // k sub-half
    const float* wcol = W + (size_t)e * (D_DIM * H_DIM) + n0 + bn;
    const uint32_t b_sts = (uint32_t)bn * 128u;
    const uint32_t b_xm = (uint32_t)(bn & 7) * 16u;

    float4 sa[8], sb[8];   // register staging for the next chunk

    // ---- consumer (ldmatrix) lane addressing ----
    const uint32_t a_lrow = (uint32_t)(warp_m * 64 + (lane & 7) + ((lane >> 3) & 1) * 8);
    const uint32_t a_sel = (uint32_t)(lane >> 4) * 16u;          // col +16B for matrices 2,3
    const uint32_t a_lxm = (uint32_t)(lane & 7) * 16u;
    const uint32_t b_lrow = (uint32_t)(warp_n * 32 + (lane & 7) + ((lane >> 4) & 1) * 8);
    const uint32_t b_sel = (uint32_t)((lane >> 3) & 1) * 16u;    // k +16B for matrices 1,3
    const uint32_t b_lxm = (uint32_t)(lane & 7) * 16u;

    float acc[4][4][4];
#pragma unroll
    for (int mt = 0; mt < 4; mt++)
#pragma unroll
        for (int nt = 0; nt < 4; nt++)
#pragma unroll
            for (int j = 0; j < 4; j++) acc[mt][nt][j] = 0.f;

    // ---- chunk 0: load + store ----
#pragma unroll
    for (int i = 0; i < 8; i++)
        sa[i] = *reinterpret_cast<const float4*>(aptr + ahalf + i * 4);
#pragma unroll
    for (int q = 0; q < 8; q++) {
        const float* wp = wcol + (size_t)(bkh + q * 4) * H_DIM;
        sb[q] = make_float4(__ldg(wp), __ldg(wp + H_DIM), __ldg(wp + 2 * H_DIM), __ldg(wp + 3 * H_DIM));
    }
    {
        const uint32_t base = buf;
#pragma unroll
        for (int i = 0; i < 8; i++) {
            uint64_t h, l; split4(sa[i], h, l);
            uint32_t col = ((uint32_t)((ahalf + i * 4) * 2)) ^ a_xm;
            STS64(base + a_sts + col, h);
            STS64(base + 16384u + a_sts + col, l);
        }
#pragma unroll
        for (int q = 0; q < 8; q++) {
            uint64_t h, l; split4(sb[q], h, l);
            uint32_t col = ((uint32_t)((bkh + q * 4) * 2)) ^ b_xm;
            STS64(base + 32768u + b_sts + col, h);
            STS64(base + 49152u + b_sts + col, l);
        }
    }
    __syncthreads();

    for (int c = 0; c < NCHUNK; c++) {
        // prefetch next chunk's globals into registers
        if (c + 1 < NCHUNK) {
            const int k0 = (c + 1) * KC;
#pragma unroll
            for (int i = 0; i < 8; i++)
                sa[i] = *reinterpret_cast<const float4*>(aptr + k0 + ahalf + i * 4);
#pragma unroll
            for (int q = 0; q < 8; q++) {
                const float* wp = wcol + (size_t)(k0 + bkh + q * 4) * H_DIM;
                sb[q] = make_float4(__ldg(wp), __ldg(wp + H_DIM), __ldg(wp + 2 * H_DIM), __ldg(wp + 3 * H_DIM));
            }
        }

        // compute current chunk
        {
            const uint32_t base = buf + (uint32_t)(c & 1) * 65536u;
            const uint32_t aH = base, aL = base + 16384u, bH = base + 32768u, bL = base + 49152u;
#pragma unroll
            for (int ks = 0; ks < 4; ks++) {
                const uint32_t acol = (uint32_t)(ks * 32) + a_sel;
                const uint32_t bcol = (uint32_t)(ks * 32) + b_sel;
                uint32_t ah[4][4], bh[2][4], bl[2][4];
#pragma unroll
                for (int mt = 0; mt < 4; mt++)
                    LDSM4(ah[mt], aH + (a_lrow + (uint32_t)mt * 16u) * 128u + (acol ^ a_lxm));
#pragma unroll
                for (int np = 0; np < 2; np++) {
                    LDSM4(bh[np], bH + (b_lrow + (uint32_t)np * 16u) * 128u + (bcol ^ b_lxm));
                    LDSM4(bl[np], bL + (b_lrow + (uint32_t)np * 16u) * 128u + (bcol ^ b_lxm));
                }
#pragma unroll
                for (int mt = 0; mt < 4; mt++)
#pragma unroll
                    for (int nt = 0; nt < 4; nt++) {
                        const uint32_t* bp = &bh[nt >> 1][(nt & 1) * 2];
                        MMA16816(acc[mt][nt], ah[mt], bp[0], bp[1]);
                        const uint32_t* bq = &bl[nt >> 1][(nt & 1) * 2];
                        MMA16816(acc[mt][nt], ah[mt], bq[0], bq[1]);
                    }
                uint32_t al[4][4];
#pragma unroll
                for (int mt = 0; mt < 4; mt++)
                    LDSM4(al[mt], aL + (a_lrow + (uint32_t)mt * 16u) * 128u + (acol ^ a_lxm));
#pragma unroll
                for (int mt = 0; mt < 4; mt++)
#pragma unroll
                    for (int nt = 0; nt < 4; nt++) {
                        const uint32_t* bp = &bh[nt >> 1][(nt & 1) * 2];
                        MMA16816(acc[mt][nt], al[mt], bp[0], bp[1]);
                    }
            }
        }
        __syncthreads();

        // stage next chunk into the other buffer
        if (c + 1 < NCHUNK) {
            const uint32_t base = buf + (uint32_t)((c + 1) & 1) * 65536u;
#pragma unroll
            for (int i = 0; i < 8; i++) {
                uint64_t h, l; split4(sa[i], h, l);
                uint32_t col = ((uint32_t)((ahalf + i * 4) * 2)) ^ a_xm;
                STS64(base + a_sts + col, h);
                STS64(base + 16384u + a_sts + col, l);
            }
#pragma unroll
            for (int q = 0; q < 8; q++) {
                uint64_t h, l; split4(sb[q], h, l);
                uint32_t col = ((uint32_t)((bkh + q * 4) * 2)) ^ b_xm;
                STS64(base + 32768u + b_sts + col, h);
                STS64(base + 49152u + b_sts + col, l);
            }
            __syncthreads();
        }
    }

    // ---- epilogue: bias (+relu), masked stores ----
    float* cbase = (LAYER == 0 ? g_h : g_y) + (size_t)e * CAPCT * 1024;
    const float* brow = bias + (size_t)e * 1024 + n0;
    const int ccol = warp_n * 32 + (lane & 3) * 2;
    const int crow = m0 + warp_m * 64 + (lane >> 2);
#pragma unroll
    for (int nt = 0; nt < 4; nt++) {
        const float b0v = __ldg(brow + ccol + nt * 8);
        const float b1v = __ldg(brow + ccol + nt * 8 + 1);
#pragma unroll
        for (int mt = 0; mt < 4; mt++) {
            const int r0 = crow + mt * 16;
            if (r0 < cnt) {
                float v0 = acc[mt][nt][0] + b0v, v1 = acc[mt][nt][1] + b1v;
                if (LAYER == 0) { v0 = fmaxf(v0, 0.f); v1 = fmaxf(v1, 0.f); }
                *reinterpret_cast<float2*>(cbase + (size_t)r0 * 1024 + n0 + ccol + nt * 8) =
                    make_float2(v0, v1);
            }
            const int r1 = r0 + 8;
            if (r1 < cnt) {
                float v0 = acc[mt][nt][2] + b0v, v1 = acc[mt][nt][3] + b1v;
                if (LAYER == 0) { v0 = fmaxf(v0, 0.f); v1 = fmaxf(v1, 0.f); }
                *reinterpret_cast<float2*>(cbase + (size_t)r1 * 1024 + n0 + ccol + nt * 8) =
                    make_float2(v0, v1);
            }
        }
    }
}

// ---------------- combine ----------------------------------------------------
__global__ void combine_kernel(float* __restrict__ out) {
    const int t = blockIdx.x;
    const int d4 = threadIdx.x;
    const int s0 = g_t_slot[t * 2 + 0];
    const int s1 = g_t_slot[t * 2 + 1];
    const float c0 = g_t_score[t * 2 + 0];
    const float c1 = g_t_score[t * 2 + 1];

    float4 r = make_float4(0.f, 0.f, 0.f, 0.f);
    if (s0 >= 0) {
        float4 a = *(reinterpret_cast<const float4*>(g_y + (size_t)s0 * D_DIM) + d4);
        r.x += c0 * a.x; r.y += c0 * a.y; r.z += c0 * a.z; r.w += c0 * a.w;
    }
    if (s1 >= 0) {
        float4 a = *(reinterpret_cast<const float4*>(g_y + (size_t)s1 * D_DIM) + d4);
        r.x += c1 * a.x; r.y += c1 * a.y; r.z += c1 * a.z; r.w += c1 * a.w;
    }
    *(reinterpret_cast<float4*>(out + (size_t)t * D_DIM) + d4) = r;
}

// ---------------- launch -----------------------------------------------------
extern "C" void kernel_launch(void* const* d_in, const int* in_sizes, int n_in,
                              void* d_out, int out_size) {
    const float* x  = (const float*)d_in[0];
    const float* Wg = (const float*)d_in[1];
    const float* bg = (const float*)d_in[2];
    const float* W1 = (const float*)d_in[3];
    const float* b1 = (const float*)d_in[4];
    const float* W2 = (const float*)d_in[5];
    const float* b2 = (const float*)d_in[6];
    float* out = (float*)d_out;

    const int SMEM_BYTES = 1024 + 2 * 65536;   // align pad + 2 stages x (Ahi,Alo,Bhi,Blo)
    cudaFuncSetAttribute(gemm_tc<0>, cudaFuncAttributeMaxDynamicSharedMemorySize, SMEM_BYTES);
    cudaFuncSetAttribute(gemm_tc<1>, cudaFuncAttributeMaxDynamicSharedMemorySize, SMEM_BYTES);

    init_kernel<<<1, 32>>>();
    gate_kernel<<<T_TOK / 4, 128>>>(x, Wg, bg);

    dim3 grid(H_DIM / BN, CAPCT / BM, E_NUM);
    gemm_tc<0><<<grid, 256, SMEM_BYTES>>>(x, W1, b1);
    gemm_tc<1><<<grid, 256, SMEM_BYTES>>>(nullptr, W2, b2);

    combine_kernel<<<T_TOK, 256>>>(out);
}

// round 6
// speedup vs baseline: 1.8762x; 1.2340x over previous
#include <cuda_runtime.h>
#include <cuda_bf16.h>
#include <cstdint>

// Problem constants
#define T_TOK 4096
#define D_DIM 1024
#define H_DIM 1024
#define E_NUM 16
#define K_TOP 2
#define CAPCT 1024

// GEMM tiling
#define BM 128
#define BN 128
#define KC 64                  // K elems per chunk
#define NCHUNK (D_DIM / KC)    // 16
#define NSTAGE 3
#define STAGE_BYTES 65536      // A_hi 16K + A_lo 16K + B_hi 16K + B_lo 16K

// ---------------- scratch (device globals; no allocations allowed) ----------
__device__ int   g_count[E_NUM];
__device__ int   g_slot_tok[E_NUM * CAPCT];
__device__ int   g_t_slot[T_TOK * K_TOP];
__device__ float g_t_score[T_TOK * K_TOP];

__device__ __nv_bfloat16 g_x_hi[(size_t)T_TOK * D_DIM];
__device__ __nv_bfloat16 g_x_lo[(size_t)T_TOK * D_DIM];
__device__ __nv_bfloat16 g_w1_hi[(size_t)E_NUM * D_DIM * H_DIM];
__device__ __nv_bfloat16 g_w1_lo[(size_t)E_NUM * D_DIM * H_DIM];
__device__ __nv_bfloat16 g_w2_hi[(size_t)E_NUM * H_DIM * D_DIM];
__device__ __nv_bfloat16 g_w2_lo[(size_t)E_NUM * H_DIM * D_DIM];
__device__ __nv_bfloat16 g_h_hi[(size_t)E_NUM * CAPCT * H_DIM];
__device__ __nv_bfloat16 g_h_lo[(size_t)E_NUM * CAPCT * H_DIM];
__device__ float         g_y[(size_t)E_NUM * CAPCT * D_DIM];

// ---------------- asm helpers ------------------------------------------------
__device__ __forceinline__ uint32_t smem_u32(const void* p) {
    uint32_t a;
    asm("{ .reg .u64 t; cvta.to.shared.u64 t, %1; cvt.u32.u64 %0, t; }" : "=r"(a) : "l"(p));
    return a;
}
#define CP16(dst, src) \
    asm volatile("cp.async.cg.shared.global [%0], [%1], 16;" :: "r"(dst), "l"(src) : "memory")
#define CP_COMMIT() asm volatile("cp.async.commit_group;" ::: "memory")
#define CP_WAIT1()  asm volatile("cp.async.wait_group 1;" ::: "memory")
#define CP_WAIT0()  asm volatile("cp.async.wait_group 0;" ::: "memory")

#define LDSM4(r, a) \
    asm volatile("ldmatrix.sync.aligned.m8n8.x4.shared.b16 {%0,%1,%2,%3}, [%4];" \
        : "=r"((r)[0]), "=r"((r)[1]), "=r"((r)[2]), "=r"((r)[3]) : "r"(a))
#define LDSM4T(r, a) \
    asm volatile("ldmatrix.sync.aligned.m8n8.x4.trans.shared.b16 {%0,%1,%2,%3}, [%4];" \
        : "=r"((r)[0]), "=r"((r)[1]), "=r"((r)[2]), "=r"((r)[3]) : "r"(a))

#define MMA16816(c, a, b0, b1) \
    asm volatile("mma.sync.aligned.m16n8k16.row.col.f32.bf16.bf16.f32 " \
        "{%0,%1,%2,%3}, {%4,%5,%6,%7}, {%8,%9}, {%0,%1,%2,%3};" \
        : "+f"((c)[0]), "+f"((c)[1]), "+f"((c)[2]), "+f"((c)[3]) \
        : "r"((a)[0]), "r"((a)[1]), "r"((a)[2]), "r"((a)[3]), "r"(b0), "r"(b1))

// ---------------- init -------------------------------------------------------
__global__ void init_kernel() {
    if (threadIdx.x < E_NUM) g_count[threadIdx.x] = 0;
}

// ---------------- split: fp32 -> bf16 hi/lo ----------------------------------
__global__ void split_kernel(const float* __restrict__ src,
                             __nv_bfloat16* __restrict__ hi,
                             __nv_bfloat16* __restrict__ lo, int n4) {
    for (int i = blockIdx.x * blockDim.x + threadIdx.x; i < n4; i += gridDim.x * blockDim.x) {
        float4 v = reinterpret_cast<const float4*>(src)[i];
        __nv_bfloat162 h0, h1, l0, l1;
        h0.x = __float2bfloat16(v.x); h0.y = __float2bfloat16(v.y);
        h1.x = __float2bfloat16(v.z); h1.y = __float2bfloat16(v.w);
        l0.x = __float2bfloat16(v.x - __bfloat162float(h0.x));
        l0.y = __float2bfloat16(v.y - __bfloat162float(h0.y));
        l1.x = __float2bfloat16(v.z - __bfloat162float(h1.x));
        l1.y = __float2bfloat16(v.w - __bfloat162float(h1.y));
        reinterpret_cast<__nv_bfloat162*>(hi)[i * 2]     = h0;
        reinterpret_cast<__nv_bfloat162*>(hi)[i * 2 + 1] = h1;
        reinterpret_cast<__nv_bfloat162*>(lo)[i * 2]     = l0;
        reinterpret_cast<__nv_bfloat162*>(lo)[i * 2 + 1] = l1;
    }
}

// ---------------- gate: one warp per token ----------------------------------
__global__ void gate_kernel(const float* __restrict__ x,
                            const float* __restrict__ Wg,
                            const float* __restrict__ bg) {
    int warp = (blockIdx.x * blockDim.x + threadIdx.x) >> 5;
    int lane = threadIdx.x & 31;
    if (warp >= T_TOK) return;
    const float* xr = x + (size_t)warp * D_DIM;

    float acc[E_NUM];
#pragma unroll
    for (int e = 0; e < E_NUM; e++) acc[e] = 0.f;

    for (int d = lane; d < D_DIM; d += 32) {
        float xv = __ldg(xr + d);
        const float4* w = reinterpret_cast<const float4*>(Wg + (size_t)d * E_NUM);
#pragma unroll
        for (int q = 0; q < 4; q++) {
            float4 wv = __ldg(w + q);
            acc[q * 4 + 0] += xv * wv.x;
            acc[q * 4 + 1] += xv * wv.y;
            acc[q * 4 + 2] += xv * wv.z;
            acc[q * 4 + 3] += xv * wv.w;
        }
    }
#pragma unroll
    for (int e = 0; e < E_NUM; e++) {
#pragma unroll
        for (int off = 16; off > 0; off >>= 1)
            acc[e] += __shfl_xor_sync(0xffffffffu, acc[e], off);
    }

    if (lane == 0) {
        float v[E_NUM];
#pragma unroll
        for (int e = 0; e < E_NUM; e++) v[e] = acc[e] + bg[e];
        int i0 = 0; float v0 = v[0];
#pragma unroll
        for (int e = 1; e < E_NUM; e++) if (v[e] > v0) { v0 = v[e]; i0 = e; }
        int i1 = -1; float v1 = -3.4e38f;
#pragma unroll
        for (int e = 0; e < E_NUM; e++)
            if (e != i0 && v[e] > v1) { v1 = v[e]; i1 = e; }
        float e1 = expf(v1 - v0);
        float s0 = 1.f / (1.f + e1);
        float s1 = e1 / (1.f + e1);

        int p0 = atomicAdd(&g_count[i0], 1);
        int p1 = atomicAdd(&g_count[i1], 1);
        if (p0 < CAPCT) {
            g_slot_tok[i0 * CAPCT + p0] = warp;
            g_t_slot[warp * 2 + 0] = i0 * CAPCT + p0;
        } else g_t_slot[warp * 2 + 0] = -1;
        if (p1 < CAPCT) {
            g_slot_tok[i1 * CAPCT + p1] = warp;
            g_t_slot[warp * 2 + 1] = i1 * CAPCT + p1;
        } else g_t_slot[warp * 2 + 1] = -1;
        g_t_score[warp * 2 + 0] = s0;
        g_t_score[warp * 2 + 1] = s1;
    }
}

// ---------------- HMMA grouped GEMM (pre-split bf16, cp.async pipeline) ------
// LAYER 0: h(bf16 hi/lo) = relu( gather(x_hi/lo) @ W1 + b1 )
// LAYER 1: g_y(fp32)     = h @ W2 + b2
// smem stage: A_hi[128][64] A_lo | B_hi[64][128] B_lo   (A m-major, B k-major)
template <int LAYER>
__global__ __launch_bounds__(256, 1)
void gemm_tc(const float* __restrict__ bias)
{
    const int e = blockIdx.z;
    int cnt = g_count[e];
    if (cnt > CAPCT) cnt = CAPCT;
    const int m0 = blockIdx.y * BM;
    if (m0 >= cnt) return;
    const int n0 = blockIdx.x * BN;

    extern __shared__ char smem[];
    const uint32_t buf = (smem_u32(smem) + 1023) & ~1023u;

    const int tid = threadIdx.x;
    const int lane = tid & 31;
    const int wid = tid >> 5;
    const int warp_m = wid >> 2;   // 0..1
    const int warp_n = wid & 3;    // 0..3

    const __nv_bfloat16* Whi = (LAYER == 0) ? g_w1_hi : g_w2_hi;
    const __nv_bfloat16* Wlo = (LAYER == 0) ? g_w1_lo : g_w2_lo;

    // ---- cp.async producer mappings ----
    // A: row = tid>>1 (0..127), segs (tid&1)*4 .. +3  (16B each, 128B rows)
    const int arow = tid >> 1;
    const int aseg0 = (tid & 1) * 4;
    const char* a_hi_row;
    const char* a_lo_row;
    if (LAYER == 0) {
        int tok = g_slot_tok[e * CAPCT + m0 + arow];   // rows >= cnt: stale but finite
        tok = min(max(tok, 0), T_TOK - 1);
        a_hi_row = (const char*)(g_x_hi + (size_t)tok * D_DIM);
        a_lo_row = (const char*)(g_x_lo + (size_t)tok * D_DIM);
    } else {
        a_hi_row = (const char*)(g_h_hi + ((size_t)e * CAPCT + m0 + arow) * H_DIM);
        a_lo_row = (const char*)(g_h_lo + ((size_t)e * CAPCT + m0 + arow) * H_DIM);
    }
    uint32_t a_dst[4];
#pragma unroll
    for (int i = 0; i < 4; i++)
        a_dst[i] = (uint32_t)arow * 128u + ((uint32_t)((aseg0 + i) * 16) ^ ((uint32_t)(arow & 7) * 16u));

    // B: krow = tid>>2 (0..63), segs (tid&3)*4 .. +3 (16B each, 256B rows, k-major)
    const int krow = tid >> 2;
    const int bseg0 = (tid & 3) * 4;
    const char* b_hi_row = (const char*)(Whi + (size_t)e * (D_DIM * H_DIM) + (size_t)krow * H_DIM + n0);
    const char* b_lo_row = (const char*)(Wlo + (size_t)e * (D_DIM * H_DIM) + (size_t)krow * H_DIM + n0);
    uint32_t b_dst[4];
#pragma unroll
    for (int i = 0; i < 4; i++)
        b_dst[i] = (uint32_t)krow * 256u + ((uint32_t)((bseg0 + i) ^ (krow & 7)) * 16u);

    // ---- consumer lane addressing ----
    const uint32_t a_lrow = (uint32_t)(warp_m * 64 + (lane & 7) + ((lane >> 3) & 1) * 8);
    const uint32_t a_sel = (uint32_t)(lane >> 4) * 16u;
    const uint32_t a_lxm = (uint32_t)(lane & 7) * 16u;
    // B trans: lane -> matrix m = lane>>3, row r = lane&7
    const uint32_t b_m = (uint32_t)(lane >> 3);
    const uint32_t b_r = (uint32_t)(lane & 7);
    const uint32_t b_rowoff = (b_m & 1) * 8 + b_r;                 // within 16-k block
    const uint32_t b_colbase = (uint32_t)warp_n * 4 + (b_m >> 1);  // 16B col index

    float acc[4][4][4];
#pragma unroll
    for (int mt = 0; mt < 4; mt++)
#pragma unroll
        for (int nt = 0; nt < 4; nt++)
#pragma unroll
            for (int j = 0; j < 4; j++) acc[mt][nt][j] = 0.f;

    // ---- issue helper (16 cp.async per thread per stage) ----
    auto issue_stage = [&](int s, int c) {
        const uint32_t sb = buf + (uint32_t)s * STAGE_BYTES;
        const size_t akb = (size_t)(c * KC) * 2;              // byte offset along A row
        const size_t bkb = (size_t)(c * KC) * (H_DIM * 2);    // byte offset along B k-rows
#pragma unroll
        for (int i = 0; i < 4; i++) {
            CP16(sb + a_dst[i],          a_hi_row + akb + (aseg0 + i) * 16);
            CP16(sb + 16384u + a_dst[i], a_lo_row + akb + (aseg0 + i) * 16);
        }
#pragma unroll
        for (int i = 0; i < 4; i++) {
            CP16(sb + 32768u + b_dst[i], b_hi_row + bkb + (bseg0 + i) * 16);
            CP16(sb + 49152u + b_dst[i], b_lo_row + bkb + (bseg0 + i) * 16);
        }
        CP_COMMIT();
    };

    issue_stage(0, 0);
    issue_stage(1, 1);

    for (int c = 0; c < NCHUNK; c++) {
        if (c < NCHUNK - 2) CP_WAIT1(); else CP_WAIT0();
        __syncthreads();
        if (c + 2 < NCHUNK) issue_stage((c + 2) % NSTAGE, c + 2);

        const uint32_t base = buf + (uint32_t)(c % NSTAGE) * STAGE_BYTES;
        const uint32_t aH = base, aL = base + 16384u, bH = base + 32768u, bL = base + 49152u;
#pragma unroll
        for (int ks = 0; ks < 4; ks++) {
            const uint32_t acol = (uint32_t)(ks * 32) + a_sel;
            const uint32_t bkrow = (uint32_t)(ks * 16) + b_rowoff;
            uint32_t ah[4][4], bh[2][4], bl[2][4];
#pragma unroll
            for (int mt = 0; mt < 4; mt++)
                LDSM4(ah[mt], aH + (a_lrow + (uint32_t)mt * 16u) * 128u + (acol ^ a_lxm));
#pragma unroll
            for (int p = 0; p < 2; p++) {
                const uint32_t boff = bkrow * 256u + (((b_colbase + (uint32_t)p * 2) ^ b_r) * 16u);
                LDSM4T(bh[p], bH + boff);
                LDSM4T(bl[p], bL + boff);
            }
#pragma unroll
            for (int mt = 0; mt < 4; mt++)
#pragma unroll
                for (int nt = 0; nt < 4; nt++) {
                    const uint32_t* bp = &bh[nt >> 1][(nt & 1) * 2];
                    MMA16816(acc[mt][nt], ah[mt], bp[0], bp[1]);
                    const uint32_t* bq = &bl[nt >> 1][(nt & 1) * 2];
                    MMA16816(acc[mt][nt], ah[mt], bq[0], bq[1]);
                }
            uint32_t al[4][4];
#pragma unroll
            for (int mt = 0; mt < 4; mt++)
                LDSM4(al[mt], aL + (a_lrow + (uint32_t)mt * 16u) * 128u + (acol ^ a_lxm));
#pragma unroll
            for (int mt = 0; mt < 4; mt++)
#pragma unroll
                for (int nt = 0; nt < 4; nt++) {
                    const uint32_t* bp = &bh[nt >> 1][(nt & 1) * 2];
                    MMA16816(acc[mt][nt], al[mt], bp[0], bp[1]);
                }
        }
    }

    // ---- epilogue ----
    const float* brow = bias + (size_t)e * 1024 + n0;
    const int ccol = warp_n * 32 + (lane & 3) * 2;
    const int crow = m0 + warp_m * 64 + (lane >> 2);
#pragma unroll
    for (int nt = 0; nt < 4; nt++) {
        const float b0v = __ldg(brow + ccol + nt * 8);
        const float b1v = __ldg(brow + ccol + nt * 8 + 1);
#pragma unroll
        for (int mt = 0; mt < 4; mt++) {
#pragma unroll
            for (int half = 0; half < 2; half++) {
                const int r = crow + mt * 16 + half * 8;
                if (r >= cnt) continue;
                float v0 = acc[mt][nt][half * 2 + 0] + b0v;
                float v1 = acc[mt][nt][half * 2 + 1] + b1v;
                const size_t idx = ((size_t)e * CAPCT + r) * 1024 + n0 + ccol + nt * 8;
                if (LAYER == 0) {
                    v0 = fmaxf(v0, 0.f); v1 = fmaxf(v1, 0.f);
                    __nv_bfloat162 hv, lv;
                    hv.x = __float2bfloat16(v0); hv.y = __float2bfloat16(v1);
                    lv.x = __float2bfloat16(v0 - __bfloat162float(hv.x));
                    lv.y = __float2bfloat16(v1 - __bfloat162float(hv.y));
                    *reinterpret_cast<__nv_bfloat162*>(g_h_hi + idx) = hv;
                    *reinterpret_cast<__nv_bfloat162*>(g_h_lo + idx) = lv;
                } else {
                    *reinterpret_cast<float2*>(g_y + idx) = make_float2(v0, v1);
                }
            }
        }
    }
}

// ---------------- combine ----------------------------------------------------
__global__ void combine_kernel(float* __restrict__ out) {
    const int t = blockIdx.x;
    const int d4 = threadIdx.x;
    const int s0 = g_t_slot[t * 2 + 0];
    const int s1 = g_t_slot[t * 2 + 1];
    const float c0 = g_t_score[t * 2 + 0];
    const float c1 = g_t_score[t * 2 + 1];

    float4 r = make_float4(0.f, 0.f, 0.f, 0.f);
    if (s0 >= 0) {
        float4 a = *(reinterpret_cast<const float4*>(g_y + (size_t)s0 * D_DIM) + d4);
        r.x += c0 * a.x; r.y += c0 * a.y; r.z += c0 * a.z; r.w += c0 * a.w;
    }
    if (s1 >= 0) {
        float4 a = *(reinterpret_cast<const float4*>(g_y + (size_t)s1 * D_DIM) + d4);
        r.x += c1 * a.x; r.y += c1 * a.y; r.z += c1 * a.z; r.w += c1 * a.w;
    }
    *(reinterpret_cast<float4*>(out + (size_t)t * D_DIM) + d4) = r;
}

// ---------------- launch -----------------------------------------------------
extern "C" void kernel_launch(void* const* d_in, const int* in_sizes, int n_in,
                              void* d_out, int out_size) {
    const float* x  = (const float*)d_in[0];
    const float* Wg = (const float*)d_in[1];
    const float* bg = (const float*)d_in[2];
    const float* W1 = (const float*)d_in[3];
    const float* b1 = (const float*)d_in[4];
    const float* W2 = (const float*)d_in[5];
    const float* b2 = (const float*)d_in[6];
    float* out = (float*)d_out;

    const int SMEM_BYTES = 1024 + NSTAGE * STAGE_BYTES;   // 197632
    cudaFuncSetAttribute(gemm_tc<0>, cudaFuncAttributeMaxDynamicSharedMemorySize, SMEM_BYTES);
    cudaFuncSetAttribute(gemm_tc<1>, cudaFuncAttributeMaxDynamicSharedMemorySize, SMEM_BYTES);

    init_kernel<<<1, 32>>>();
    gate_kernel<<<T_TOK / 4, 128>>>(x, Wg, bg);

    // pre-split inputs and weights into bf16 hi/lo
    __nv_bfloat16 *xh, *xl, *w1h, *w1l, *w2h, *w2l;
    cudaGetSymbolAddress((void**)&xh, g_x_hi);
    cudaGetSymbolAddress((void**)&xl, g_x_lo);
    cudaGetSymbolAddress((void**)&w1h, g_w1_hi);
    cudaGetSymbolAddress((void**)&w1l, g_w1_lo);
    cudaGetSymbolAddress((void**)&w2h, g_w2_hi);
    cudaGetSymbolAddress((void**)&w2l, g_w2_lo);
    split_kernel<<<1024, 256>>>(x,  xh,  xl,  (T_TOK * D_DIM) / 4);
    split_kernel<<<2048, 256>>>(W1, w1h, w1l, (E_NUM * D_DIM * H_DIM) / 4);
    split_kernel<<<2048, 256>>>(W2, w2h, w2l, (E_NUM * H_DIM * D_DIM) / 4);

    dim3 grid(H_DIM / BN, CAPCT / BM, E_NUM);
    gemm_tc<0><<<grid, 256, SMEM_BYTES>>>(b1);
    gemm_tc<1><<<grid, 256, SMEM_BYTES>>>(b2);

    combine_kernel<<<T_TOK, 256>>>(out);
}

// round 7
// speedup vs baseline: 1.8845x; 1.0044x over previous
#include <cuda_runtime.h>
#include <cuda_bf16.h>
#include <cstdint>

// Problem constants
#define T_TOK 4096
#define D_DIM 1024
#define H_DIM 1024
#define E_NUM 16
#define K_TOP 2
#define CAPCT 1024

// GEMM tiling
#define BM 128
#define BN 128
#define KC 64                  // K elems per chunk
#define NCHUNK (D_DIM / KC)    // 16
#define NSTAGE 3
#define STAGE_BYTES 65536      // A_hi 16K + A_lo 16K + B_hi 16K + B_lo 16K

#define NX4 ((T_TOK * D_DIM) / 4)
#define NW4 ((E_NUM * D_DIM * H_DIM) / 4)

// ---------------- scratch (device globals; no allocations allowed) ----------
__device__ int   g_count[E_NUM];
__device__ int   g_slot_tok[E_NUM * CAPCT];
__device__ float g_slot_score[E_NUM * CAPCT];

__device__ __nv_bfloat16 g_x_hi[(size_t)T_TOK * D_DIM];
__device__ __nv_bfloat16 g_x_lo[(size_t)T_TOK * D_DIM];
__device__ __nv_bfloat16 g_w1_hi[(size_t)E_NUM * D_DIM * H_DIM];
__device__ __nv_bfloat16 g_w1_lo[(size_t)E_NUM * D_DIM * H_DIM];
__device__ __nv_bfloat16 g_w2_hi[(size_t)E_NUM * H_DIM * D_DIM];
__device__ __nv_bfloat16 g_w2_lo[(size_t)E_NUM * H_DIM * D_DIM];
__device__ __nv_bfloat16 g_h_hi[(size_t)E_NUM * CAPCT * H_DIM];
__device__ __nv_bfloat16 g_h_lo[(size_t)E_NUM * CAPCT * H_DIM];

// ---------------- asm helpers ------------------------------------------------
__device__ __forceinline__ uint32_t smem_u32(const void* p) {
    uint32_t a;
    asm("{ .reg .u64 t; cvta.to.shared.u64 t, %1; cvt.u32.u64 %0, t; }" : "=r"(a) : "l"(p));
    return a;
}
#define CP16(dst, src) \
    asm volatile("cp.async.cg.shared.global [%0], [%1], 16;" :: "r"(dst), "l"(src) : "memory")
#define CP_COMMIT() asm volatile("cp.async.commit_group;" ::: "memory")
#define CP_WAIT1()  asm volatile("cp.async.wait_group 1;" ::: "memory")
#define CP_WAIT0()  asm volatile("cp.async.wait_group 0;" ::: "memory")

#define LDSM4(r, a) \
    asm volatile("ldmatrix.sync.aligned.m8n8.x4.shared.b16 {%0,%1,%2,%3}, [%4];" \
        : "=r"((r)[0]), "=r"((r)[1]), "=r"((r)[2]), "=r"((r)[3]) : "r"(a))
#define LDSM4T(r, a) \
    asm volatile("ldmatrix.sync.aligned.m8n8.x4.trans.shared.b16 {%0,%1,%2,%3}, [%4];" \
        : "=r"((r)[0]), "=r"((r)[1]), "=r"((r)[2]), "=r"((r)[3]) : "r"(a))

#define MMA16816(c, a, b0, b1) \
    asm volatile("mma.sync.aligned.m16n8k16.row.col.f32.bf16.bf16.f32 " \
        "{%0,%1,%2,%3}, {%4,%5,%6,%7}, {%8,%9}, {%0,%1,%2,%3};" \
        : "+f"((c)[0]), "+f"((c)[1]), "+f"((c)[2]), "+f"((c)[3]) \
        : "r"((a)[0]), "r"((a)[1]), "r"((a)[2]), "r"((a)[3]), "r"(b0), "r"(b1))

// split fp32x4 -> packed hi/lo bf16x4 (u64 each)
__device__ __forceinline__ void split4(float4 v, unsigned long long& hi, unsigned long long& lo) {
    __nv_bfloat16 h0 = __float2bfloat16(v.x), h1 = __float2bfloat16(v.y);
    __nv_bfloat16 h2 = __float2bfloat16(v.z), h3 = __float2bfloat16(v.w);
    __nv_bfloat16 l0 = __float2bfloat16(v.x - __bfloat162float(h0));
    __nv_bfloat16 l1 = __float2bfloat16(v.y - __bfloat162float(h1));
    __nv_bfloat16 l2 = __float2bfloat16(v.z - __bfloat162float(h2));
    __nv_bfloat16 l3 = __float2bfloat16(v.w - __bfloat162float(h3));
    hi = (unsigned long long)__bfloat16_as_ushort(h0)
       | ((unsigned long long)__bfloat16_as_ushort(h1) << 16)
       | ((unsigned long long)__bfloat16_as_ushort(h2) << 32)
       | ((unsigned long long)__bfloat16_as_ushort(h3) << 48);
    lo = (unsigned long long)__bfloat16_as_ushort(l0)
       | ((unsigned long long)__bfloat16_as_ushort(l1) << 16)
       | ((unsigned long long)__bfloat16_as_ushort(l2) << 32)
       | ((unsigned long long)__bfloat16_as_ushort(l3) << 48);
}

// ---------------- init: zero counters + output -------------------------------
__global__ void init_zero(float* __restrict__ out) {
    const size_t i = (size_t)blockIdx.x * blockDim.x + threadIdx.x;
    if (i < NX4) reinterpret_cast<float4*>(out)[i] = make_float4(0.f, 0.f, 0.f, 0.f);
    if (blockIdx.x == 0 && threadIdx.x < E_NUM) g_count[threadIdx.x] = 0;
}

// ---------------- split all three fp32 tensors -> bf16 hi/lo -----------------
__global__ void split_all(const float* __restrict__ x,
                          const float* __restrict__ W1,
                          const float* __restrict__ W2) {
    const size_t i = (size_t)blockIdx.x * blockDim.x + threadIdx.x;
    const float4* src;
    unsigned long long *hi, *lo;
    size_t off;
    if (i < NX4) {
        src = reinterpret_cast<const float4*>(x);
        hi = reinterpret_cast<unsigned long long*>(g_x_hi);
        lo = reinterpret_cast<unsigned long long*>(g_x_lo);
        off = i;
    } else if (i < NX4 + NW4) {
        src = reinterpret_cast<const float4*>(W1);
        hi = reinterpret_cast<unsigned long long*>(g_w1_hi);
        lo = reinterpret_cast<unsigned long long*>(g_w1_lo);
        off = i - NX4;
    } else if (i < NX4 + 2 * NW4) {
        src = reinterpret_cast<const float4*>(W2);
        hi = reinterpret_cast<unsigned long long*>(g_w2_hi);
        lo = reinterpret_cast<unsigned long long*>(g_w2_lo);
        off = i - NX4 - NW4;
    } else {
        return;
    }
    float4 v = __ldcs(src + off);
    unsigned long long h, l;
    split4(v, h, l);
    __stcs(hi + off, h);
    __stcs(lo + off, l);
}

// ---------------- gate: one warp per token ----------------------------------
__global__ void gate_kernel(const float* __restrict__ x,
                            const float* __restrict__ Wg,
                            const float* __restrict__ bg) {
    int warp = (blockIdx.x * blockDim.x + threadIdx.x) >> 5;
    int lane = threadIdx.x & 31;
    if (warp >= T_TOK) return;
    const float* xr = x + (size_t)warp * D_DIM;

    float acc[E_NUM];
#pragma unroll
    for (int e = 0; e < E_NUM; e++) acc[e] = 0.f;

    for (int d = lane; d < D_DIM; d += 32) {
        float xv = __ldg(xr + d);
        const float4* w = reinterpret_cast<const float4*>(Wg + (size_t)d * E_NUM);
#pragma unroll
        for (int q = 0; q < 4; q++) {
            float4 wv = __ldg(w + q);
            acc[q * 4 + 0] += xv * wv.x;
            acc[q * 4 + 1] += xv * wv.y;
            acc[q * 4 + 2] += xv * wv.z;
            acc[q * 4 + 3] += xv * wv.w;
        }
    }
#pragma unroll
    for (int e = 0; e < E_NUM; e++) {
#pragma unroll
        for (int off = 16; off > 0; off >>= 1)
            acc[e] += __shfl_xor_sync(0xffffffffu, acc[e], off);
    }

    if (lane == 0) {
        float v[E_NUM];
#pragma unroll
        for (int e = 0; e < E_NUM; e++) v[e] = acc[e] + bg[e];
        int i0 = 0; float v0 = v[0];
#pragma unroll
        for (int e = 1; e < E_NUM; e++) if (v[e] > v0) { v0 = v[e]; i0 = e; }
        int i1 = -1; float v1 = -3.4e38f;
#pragma unroll
        for (int e = 0; e < E_NUM; e++)
            if (e != i0 && v[e] > v1) { v1 = v[e]; i1 = e; }
        float e1 = expf(v1 - v0);
        float s0 = 1.f / (1.f + e1);
        float s1 = e1 / (1.f + e1);

        int p0 = atomicAdd(&g_count[i0], 1);
        int p1 = atomicAdd(&g_count[i1], 1);
        if (p0 < CAPCT) {
            g_slot_tok[i0 * CAPCT + p0] = warp;
            g_slot_score[i0 * CAPCT + p0] = s0;
        }
        if (p1 < CAPCT) {
            g_slot_tok[i1 * CAPCT + p1] = warp;
            g_slot_score[i1 * CAPCT + p1] = s1;
        }
    }
}

// ---------------- HMMA grouped GEMM (pre-split bf16, cp.async pipeline) ------
// LAYER 0: h(bf16 hi/lo) = relu( gather(x_hi/lo) @ W1 + b1 )
// LAYER 1: out[tok] += score * ( h @ W2 + b2 )   (atomic combine)
template <int LAYER>
__global__ __launch_bounds__(256, 1)
void gemm_tc(const float* __restrict__ bias, float* __restrict__ out)
{
    const int e = blockIdx.z;
    int cnt = g_count[e];
    if (cnt > CAPCT) cnt = CAPCT;
    const int m0 = blockIdx.x * BM;       // x = m-tile: consecutive CTAs share W slab
    if (m0 >= cnt) return;
    const int n0 = blockIdx.y * BN;

    extern __shared__ char smem[];
    const uint32_t buf = (smem_u32(smem) + 1023) & ~1023u;

    const int tid = threadIdx.x;
    const int lane = tid & 31;
    const int wid = tid >> 5;
    const int warp_m = wid >> 2;   // 0..1
    const int warp_n = wid & 3;    // 0..3

    const __nv_bfloat16* Whi = (LAYER == 0) ? g_w1_hi : g_w2_hi;
    const __nv_bfloat16* Wlo = (LAYER == 0) ? g_w1_lo : g_w2_lo;

    // ---- cp.async producer mappings ----
    const int arow = tid >> 1;
    const int aseg0 = (tid & 1) * 4;
    const char* a_hi_row;
    const char* a_lo_row;
    if (LAYER == 0) {
        int tok = g_slot_tok[e * CAPCT + m0 + arow];   // rows >= cnt: stale but finite
        tok = min(max(tok, 0), T_TOK - 1);
        a_hi_row = (const char*)(g_x_hi + (size_t)tok * D_DIM);
        a_lo_row = (const char*)(g_x_lo + (size_t)tok * D_DIM);
    } else {
        a_hi_row = (const char*)(g_h_hi + ((size_t)e * CAPCT + m0 + arow) * H_DIM);
        a_lo_row = (const char*)(g_h_lo + ((size_t)e * CAPCT + m0 + arow) * H_DIM);
    }
    uint32_t a_dst[4];
#pragma unroll
    for (int i = 0; i < 4; i++)
        a_dst[i] = (uint32_t)arow * 128u + ((uint32_t)((aseg0 + i) * 16) ^ ((uint32_t)(arow & 7) * 16u));

    const int krow = tid >> 2;
    const int bseg0 = (tid & 3) * 4;
    const char* b_hi_row = (const char*)(Whi + (size_t)e * (D_DIM * H_DIM) + (size_t)krow * H_DIM + n0);
    const char* b_lo_row = (const char*)(Wlo + (size_t)e * (D_DIM * H_DIM) + (size_t)krow * H_DIM + n0);
    uint32_t b_dst[4];
#pragma unroll
    for (int i = 0; i < 4; i++)
        b_dst[i] = (uint32_t)krow * 256u + ((uint32_t)((bseg0 + i) ^ (krow & 7)) * 16u);

    // ---- consumer lane addressing ----
    const uint32_t a_lrow = (uint32_t)(warp_m * 64 + (lane & 7) + ((lane >> 3) & 1) * 8);
    const uint32_t a_sel = (uint32_t)(lane >> 4) * 16u;
    const uint32_t a_lxm = (uint32_t)(lane & 7) * 16u;
    const uint32_t b_m = (uint32_t)(lane >> 3);
    const uint32_t b_r = (uint32_t)(lane & 7);
    const uint32_t b_rowoff = (b_m & 1) * 8 + b_r;
    const uint32_t b_colbase = (uint32_t)warp_n * 4 + (b_m >> 1);

    float acc[4][4][4];
#pragma unroll
    for (int mt = 0; mt < 4; mt++)
#pragma unroll
        for (int nt = 0; nt < 4; nt++)
#pragma unroll
            for (int j = 0; j < 4; j++) acc[mt][nt][j] = 0.f;

    auto issue_stage = [&](int s, int c) {
        const uint32_t sb = buf + (uint32_t)s * STAGE_BYTES;
        const size_t akb = (size_t)(c * KC) * 2;
        const size_t bkb = (size_t)(c * KC) * (H_DIM * 2);
#pragma unroll
        for (int i = 0; i < 4; i++) {
            CP16(sb + a_dst[i],          a_hi_row + akb + (aseg0 + i) * 16);
            CP16(sb + 16384u + a_dst[i], a_lo_row + akb + (aseg0 + i) * 16);
        }
#pragma unroll
        for (int i = 0; i < 4; i++) {
            CP16(sb + 32768u + b_dst[i], b_hi_row + bkb + (bseg0 + i) * 16);
            CP16(sb + 49152u + b_dst[i], b_lo_row + bkb + (bseg0 + i) * 16);
        }
        CP_COMMIT();
    };

    issue_stage(0, 0);
    issue_stage(1, 1);

    for (int c = 0; c < NCHUNK; c++) {
        if (c < NCHUNK - 2) CP_WAIT1(); else CP_WAIT0();
        __syncthreads();
        if (c + 2 < NCHUNK) issue_stage((c + 2) % NSTAGE, c + 2);

        const uint32_t base = buf + (uint32_t)(c % NSTAGE) * STAGE_BYTES;
        const uint32_t aH = base, aL = base + 16384u, bH = base + 32768u, bL = base + 49152u;
#pragma unroll
        for (int ks = 0; ks < 4; ks++) {
            const uint32_t acol = (uint32_t)(ks * 32) + a_sel;
            const uint32_t bkrow = (uint32_t)(ks * 16) + b_rowoff;
            uint32_t ah[4][4], bh[2][4], bl[2][4];
#pragma unroll
            for (int mt = 0; mt < 4; mt++)
                LDSM4(ah[mt], aH + (a_lrow + (uint32_t)mt * 16u) * 128u + (acol ^ a_lxm));
#pragma unroll
            for (int p = 0; p < 2; p++) {
                const uint32_t boff = bkrow * 256u + (((b_colbase + (uint32_t)p * 2) ^ b_r) * 16u);
                LDSM4T(bh[p], bH + boff);
                LDSM4T(bl[p], bL + boff);
            }
#pragma unroll
            for (int mt = 0; mt < 4; mt++)
#pragma unroll
                for (int nt = 0; nt < 4; nt++) {
                    const uint32_t* bp = &bh[nt >> 1][(nt & 1) * 2];
                    MMA16816(acc[mt][nt], ah[mt], bp[0], bp[1]);
                    const uint32_t* bq = &bl[nt >> 1][(nt & 1) * 2];
                    MMA16816(acc[mt][nt], ah[mt], bq[0], bq[1]);
                }
            uint32_t al[4][4];
#pragma unroll
            for (int mt = 0; mt < 4; mt++)
                LDSM4(al[mt], aL + (a_lrow + (uint32_t)mt * 16u) * 128u + (acol ^ a_lxm));
#pragma unroll
            for (int mt = 0; mt < 4; mt++)
#pragma unroll
                for (int nt = 0; nt < 4; nt++) {
                    const uint32_t* bp = &bh[nt >> 1][(nt & 1) * 2];
                    MMA16816(acc[mt][nt], al[mt], bp[0], bp[1]);
                }
        }
    }

    // ---- epilogue ----
    const float* brow = bias + (size_t)e * 1024 + n0;
    const int ccol = warp_n * 32 + (lane & 3) * 2;
    const int crow = m0 + warp_m * 64 + (lane >> 2);
    float bv[8];
#pragma unroll
    for (int nt = 0; nt < 4; nt++) {
        bv[nt * 2 + 0] = __ldg(brow + ccol + nt * 8);
        bv[nt * 2 + 1] = __ldg(brow + ccol + nt * 8 + 1);
    }

#pragma unroll
    for (int mt = 0; mt < 4; mt++) {
#pragma unroll
        for (int half = 0; half < 2; half++) {
            const int r = crow + mt * 16 + half * 8;
            if (r >= cnt) continue;
            if (LAYER == 0) {
                const size_t idx = ((size_t)e * CAPCT + r) * 1024 + n0 + ccol;
#pragma unroll
                for (int nt = 0; nt < 4; nt++) {
                    float v0 = fmaxf(acc[mt][nt][half * 2 + 0] + bv[nt * 2 + 0], 0.f);
                    float v1 = fmaxf(acc[mt][nt][half * 2 + 1] + bv[nt * 2 + 1], 0.f);
                    __nv_bfloat162 hv, lv;
                    hv.x = __float2bfloat16(v0); hv.y = __float2bfloat16(v1);
                    lv.x = __float2bfloat16(v0 - __bfloat162float(hv.x));
                    lv.y = __float2bfloat16(v1 - __bfloat162float(hv.y));
                    *reinterpret_cast<__nv_bfloat162*>(g_h_hi + idx + nt * 8) = hv;
                    *reinterpret_cast<__nv_bfloat162*>(g_h_lo + idx + nt * 8) = lv;
                }
            } else {
                const int slot = e * CAPCT + r;
                const int tok = g_slot_tok[slot];
                const float sc = g_slot_score[slot];
                float* orow = out + (size_t)tok * 1024 + n0 + ccol;
#pragma unroll
                for (int nt = 0; nt < 4; nt++) {
                    atomicAdd(orow + nt * 8,     sc * (acc[mt][nt][half * 2 + 0] + bv[nt * 2 + 0]));
                    atomicAdd(orow + nt * 8 + 1, sc * (acc[mt][nt][half * 2 + 1] + bv[nt * 2 + 1]));
                }
            }
        }
    }
}

// ---------------- launch -----------------------------------------------------
extern "C" void kernel_launch(void* const* d_in, const int* in_sizes, int n_in,
                              void* d_out, int out_size) {
    const float* x  = (const float*)d_in[0];
    const float* Wg = (const float*)d_in[1];
    const float* bg = (const float*)d_in[2];
    const float* W1 = (const float*)d_in[3];
    const float* b1 = (const float*)d_in[4];
    const float* W2 = (const float*)d_in[5];
    const float* b2 = (const float*)d_in[6];
    float* out = (float*)d_out;

    const int SMEM_BYTES = 1024 + NSTAGE * STAGE_BYTES;   // 197632
    cudaFuncSetAttribute(gemm_tc<0>, cudaFuncAttributeMaxDynamicSharedMemorySize, SMEM_BYTES);
    cudaFuncSetAttribute(gemm_tc<1>, cudaFuncAttributeMaxDynamicSharedMemorySize, SMEM_BYTES);

    init_zero<<<(NX4 + 255) / 256, 256>>>(out);
    gate_kernel<<<T_TOK / 4, 128>>>(x, Wg, bg);
    split_all<<<(NX4 + 2 * NW4 + 255) / 256, 256>>>(x, W1, W2);

    dim3 grid(CAPCT / BM, H_DIM / BN, E_NUM);   // x = m-tile (fast), y = n-tile, z = expert
    gemm_tc<0><<<grid, 256, SMEM_BYTES>>>(b1, nullptr);
    gemm_tc<1><<<grid, 256, SMEM_BYTES>>>(b2, out);
}

// round 8
// speedup vs baseline: 1.8887x; 1.0023x over previous
#include <cuda_runtime.h>
#include <cuda_bf16.h>
#include <cstdint>

// Problem constants
#define T_TOK 4096
#define D_DIM 1024
#define H_DIM 1024
#define E_NUM 16
#define K_TOP 2
#define CAPCT 1024

// GEMM tiling
#define BM 128
#define BN 128
#define KC 64                  // K elems per chunk
#define NCHUNK (D_DIM / KC)    // 16
#define NSTAGE 3
#define STAGE_BYTES 65536      // A_hi 16K + A_lo 16K + B_hi 16K + B_lo 16K

#define NX4 ((T_TOK * D_DIM) / 4)
#define NW4 ((E_NUM * D_DIM * H_DIM) / 4)

// ---------------- scratch (device globals; no allocations allowed) ----------
__device__ int   g_count[E_NUM];
__device__ int   g_slot_tok[E_NUM * CAPCT];
__device__ float g_slot_score[E_NUM * CAPCT];

__device__ __nv_bfloat16 g_x_hi[(size_t)T_TOK * D_DIM];
__device__ __nv_bfloat16 g_x_lo[(size_t)T_TOK * D_DIM];
__device__ __nv_bfloat16 g_w1_hi[(size_t)E_NUM * D_DIM * H_DIM];
__device__ __nv_bfloat16 g_w1_lo[(size_t)E_NUM * D_DIM * H_DIM];
__device__ __nv_bfloat16 g_w2_hi[(size_t)E_NUM * H_DIM * D_DIM];
__device__ __nv_bfloat16 g_w2_lo[(size_t)E_NUM * H_DIM * D_DIM];
__device__ __nv_bfloat16 g_h_hi[(size_t)E_NUM * CAPCT * H_DIM];
__device__ __nv_bfloat16 g_h_lo[(size_t)E_NUM * CAPCT * H_DIM];

// ---------------- asm helpers ------------------------------------------------
__device__ __forceinline__ uint32_t smem_u32(const void* p) {
    uint32_t a;
    asm("{ .reg .u64 t; cvta.to.shared.u64 t, %1; cvt.u32.u64 %0, t; }" : "=r"(a) : "l"(p));
    return a;
}
#define CP16(dst, src) \
    asm volatile("cp.async.cg.shared.global [%0], [%1], 16;" :: "r"(dst), "l"(src) : "memory")
#define CP_COMMIT() asm volatile("cp.async.commit_group;" ::: "memory")
#define CP_WAIT1()  asm volatile("cp.async.wait_group 1;" ::: "memory")
#define CP_WAIT0()  asm volatile("cp.async.wait_group 0;" ::: "memory")

#define LDSM4(r, a) \
    asm volatile("ldmatrix.sync.aligned.m8n8.x4.shared.b16 {%0,%1,%2,%3}, [%4];" \
        : "=r"((r)[0]), "=r"((r)[1]), "=r"((r)[2]), "=r"((r)[3]) : "r"(a))
#define LDSM4T(r, a) \
    asm volatile("ldmatrix.sync.aligned.m8n8.x4.trans.shared.b16 {%0,%1,%2,%3}, [%4];" \
        : "=r"((r)[0]), "=r"((r)[1]), "=r"((r)[2]), "=r"((r)[3]) : "r"(a))

#define MMA16816(c, a, b0, b1) \
    asm volatile("mma.sync.aligned.m16n8k16.row.col.f32.bf16.bf16.f32 " \
        "{%0,%1,%2,%3}, {%4,%5,%6,%7}, {%8,%9}, {%0,%1,%2,%3};" \
        : "+f"((c)[0]), "+f"((c)[1]), "+f"((c)[2]), "+f"((c)[3]) \
        : "r"((a)[0]), "r"((a)[1]), "r"((a)[2]), "r"((a)[3]), "r"(b0), "r"(b1))

// split fp32x4 -> packed hi/lo bf16x4 (u64 each)
__device__ __forceinline__ void split4(float4 v, unsigned long long& hi, unsigned long long& lo) {
    __nv_bfloat16 h0 = __float2bfloat16(v.x), h1 = __float2bfloat16(v.y);
    __nv_bfloat16 h2 = __float2bfloat16(v.z), h3 = __float2bfloat16(v.w);
    __nv_bfloat16 l0 = __float2bfloat16(v.x - __bfloat162float(h0));
    __nv_bfloat16 l1 = __float2bfloat16(v.y - __bfloat162float(h1));
    __nv_bfloat16 l2 = __float2bfloat16(v.z - __bfloat162float(h2));
    __nv_bfloat16 l3 = __float2bfloat16(v.w - __bfloat162float(h3));
    hi = (unsigned long long)__bfloat16_as_ushort(h0)
       | ((unsigned long long)__bfloat16_as_ushort(h1) << 16)
       | ((unsigned long long)__bfloat16_as_ushort(h2) << 32)
       | ((unsigned long long)__bfloat16_as_ushort(h3) << 48);
    lo = (unsigned long long)__bfloat16_as_ushort(l0)
       | ((unsigned long long)__bfloat16_as_ushort(l1) << 16)
       | ((unsigned long long)__bfloat16_as_ushort(l2) << 32)
       | ((unsigned long long)__bfloat16_as_ushort(l3) << 48);
}

// ---------------- init: zero counters + output -------------------------------
__global__ void init_zero(float* __restrict__ out) {
    const size_t i = (size_t)blockIdx.x * blockDim.x + threadIdx.x;
    if (i < NX4) reinterpret_cast<float4*>(out)[i] = make_float4(0.f, 0.f, 0.f, 0.f);
    if (blockIdx.x == 0 && threadIdx.x < E_NUM) g_count[threadIdx.x] = 0;
}

// ---------------- split all three fp32 tensors -> bf16 hi/lo -----------------
__global__ void split_all(const float* __restrict__ x,
                          const float* __restrict__ W1,
                          const float* __restrict__ W2) {
    const size_t i = (size_t)blockIdx.x * blockDim.x + threadIdx.x;
    const float4* src;
    unsigned long long *hi, *lo;
    size_t off;
    if (i < NX4) {
        src = reinterpret_cast<const float4*>(x);
        hi = reinterpret_cast<unsigned long long*>(g_x_hi);
        lo = reinterpret_cast<unsigned long long*>(g_x_lo);
        off = i;
    } else if (i < NX4 + NW4) {
        src = reinterpret_cast<const float4*>(W1);
        hi = reinterpret_cast<unsigned long long*>(g_w1_hi);
        lo = reinterpret_cast<unsigned long long*>(g_w1_lo);
        off = i - NX4;
    } else if (i < NX4 + 2 * NW4) {
        src = reinterpret_cast<const float4*>(W2);
        hi = reinterpret_cast<unsigned long long*>(g_w2_hi);
        lo = reinterpret_cast<unsigned long long*>(g_w2_lo);
        off = i - NX4 - NW4;
    } else {
        return;
    }
    float4 v = __ldcs(src + off);
    unsigned long long h, l;
    split4(v, h, l);
    __stcs(hi + off, h);
    __stcs(lo + off, l);
}

// ---------------- gate: one warp per token ----------------------------------
__global__ void gate_kernel(const float* __restrict__ x,
                            const float* __restrict__ Wg,
                            const float* __restrict__ bg) {
    int warp = (blockIdx.x * blockDim.x + threadIdx.x) >> 5;
    int lane = threadIdx.x & 31;
    if (warp >= T_TOK) return;
    const float* xr = x + (size_t)warp * D_DIM;

    float acc[E_NUM];
#pragma unroll
    for (int e = 0; e < E_NUM; e++) acc[e] = 0.f;

    for (int d = lane; d < D_DIM; d += 32) {
        float xv = __ldg(xr + d);
        const float4* w = reinterpret_cast<const float4*>(Wg + (size_t)d * E_NUM);
#pragma unroll
        for (int q = 0; q < 4; q++) {
            float4 wv = __ldg(w + q);
            acc[q * 4 + 0] += xv * wv.x;
            acc[q * 4 + 1] += xv * wv.y;
            acc[q * 4 + 2] += xv * wv.z;
            acc[q * 4 + 3] += xv * wv.w;
        }
    }
#pragma unroll
    for (int e = 0; e < E_NUM; e++) {
#pragma unroll
        for (int off = 16; off > 0; off >>= 1)
            acc[e] += __shfl_xor_sync(0xffffffffu, acc[e], off);
    }

    if (lane == 0) {
        float v[E_NUM];
#pragma unroll
        for (int e = 0; e < E_NUM; e++) v[e] = acc[e] + bg[e];
        int i0 = 0; float v0 = v[0];
#pragma unroll
        for (int e = 1; e < E_NUM; e++) if (v[e] > v0) { v0 = v[e]; i0 = e; }
        int i1 = -1; float v1 = -3.4e38f;
#pragma unroll
        for (int e = 0; e < E_NUM; e++)
            if (e != i0 && v[e] > v1) { v1 = v[e]; i1 = e; }
        float e1 = expf(v1 - v0);
        float s0 = 1.f / (1.f + e1);
        float s1 = e1 / (1.f + e1);

        int p0 = atomicAdd(&g_count[i0], 1);
        int p1 = atomicAdd(&g_count[i1], 1);
        if (p0 < CAPCT) {
            g_slot_tok[i0 * CAPCT + p0] = warp;
            g_slot_score[i0 * CAPCT + p0] = s0;
        }
        if (p1 < CAPCT) {
            g_slot_tok[i1 * CAPCT + p1] = warp;
            g_slot_score[i1 * CAPCT + p1] = s1;
        }
    }
}

// ---------------- HMMA grouped GEMM (pre-split bf16, cp.async pipeline) ------
// LAYER 0: h(bf16 hi/lo) = relu( gather(x_hi/lo) @ W1 + b1 )
// LAYER 1: out[tok] += score * ( h @ W2 + b2 )   (atomic combine)
template <int LAYER>
__global__ __launch_bounds__(256, 1)
void gemm_tc(const float* __restrict__ bias, float* __restrict__ out)
{
    const int e = blockIdx.z;
    int cnt = g_count[e];
    if (cnt > CAPCT) cnt = CAPCT;
    const int m0 = blockIdx.x * BM;       // x = m-tile: consecutive CTAs share W slab
    if (m0 >= cnt) return;
    const int n0 = blockIdx.y * BN;

    extern __shared__ char smem[];
    const uint32_t buf = (smem_u32(smem) + 1023) & ~1023u;

    const int tid = threadIdx.x;
    const int lane = tid & 31;
    const int wid = tid >> 5;
    const int warp_m = wid >> 2;   // 0..1
    const int warp_n = wid & 3;    // 0..3

    const __nv_bfloat16* Whi = (LAYER == 0) ? g_w1_hi : g_w2_hi;
    const __nv_bfloat16* Wlo = (LAYER == 0) ? g_w1_lo : g_w2_lo;

    // ---- cp.async producer mappings ----
    const int arow = tid >> 1;
    const int aseg0 = (tid & 1) * 4;
    const char* a_hi_row;
    const char* a_lo_row;
    if (LAYER == 0) {
        int tok = g_slot_tok[e * CAPCT + m0 + arow];   // rows >= cnt: stale but finite
        tok = min(max(tok, 0), T_TOK - 1);
        a_hi_row = (const char*)(g_x_hi + (size_t)tok * D_DIM);
        a_lo_row = (const char*)(g_x_lo + (size_t)tok * D_DIM);
    } else {
        a_hi_row = (const char*)(g_h_hi + ((size_t)e * CAPCT + m0 + arow) * H_DIM);
        a_lo_row = (const char*)(g_h_lo + ((size_t)e * CAPCT + m0 + arow) * H_DIM);
    }
    uint32_t a_dst[4];
#pragma unroll
    for (int i = 0; i < 4; i++)
        a_dst[i] = (uint32_t)arow * 128u + ((uint32_t)((aseg0 + i) * 16) ^ ((uint32_t)(arow & 7) * 16u));

    const int krow = tid >> 2;
    const int bseg0 = (tid & 3) * 4;
    const char* b_hi_row = (const char*)(Whi + (size_t)e * (D_DIM * H_DIM) + (size_t)krow * H_DIM + n0);
    const char* b_lo_row = (const char*)(Wlo + (size_t)e * (D_DIM * H_DIM) + (size_t)krow * H_DIM + n0);
    uint32_t b_dst[4];
#pragma unroll
    for (int i = 0; i < 4; i++)
        b_dst[i] = (uint32_t)krow * 256u + ((uint32_t)((bseg0 + i) ^ (krow & 7)) * 16u);

    // ---- consumer lane addressing ----
    const uint32_t a_lrow = (uint32_t)(warp_m * 64 + (lane & 7) + ((lane >> 3) & 1) * 8);
    const uint32_t a_sel = (uint32_t)(lane >> 4) * 16u;
    const uint32_t a_lxm = (uint32_t)(lane & 7) * 16u;
    const uint32_t b_m = (uint32_t)(lane >> 3);
    const uint32_t b_r = (uint32_t)(lane & 7);
    const uint32_t b_rowoff = (b_m & 1) * 8 + b_r;
    const uint32_t b_colbase = (uint32_t)warp_n * 4 + (b_m >> 1);

    float acc[4][4][4];
#pragma unroll
    for (int mt = 0; mt < 4; mt++)
#pragma unroll
        for (int nt = 0; nt < 4; nt++)
#pragma unroll
            for (int j = 0; j < 4; j++) acc[mt][nt][j] = 0.f;

    auto issue_stage = [&](int s, int c) {
        const uint32_t sb = buf + (uint32_t)s * STAGE_BYTES;
        const size_t akb = (size_t)(c * KC) * 2;
        const size_t bkb = (size_t)(c * KC) * (H_DIM * 2);
#pragma unroll
        for (int i = 0; i < 4; i++) {
            CP16(sb + a_dst[i],          a_hi_row + akb + (aseg0 + i) * 16);
            CP16(sb + 16384u + a_dst[i], a_lo_row + akb + (aseg0 + i) * 16);
        }
#pragma unroll
        for (int i = 0; i < 4; i++) {
            CP16(sb + 32768u + b_dst[i], b_hi_row + bkb + (bseg0 + i) * 16);
            CP16(sb + 49152u + b_dst[i], b_lo_row + bkb + (bseg0 + i) * 16);
        }
        CP_COMMIT();
    };

    issue_stage(0, 0);
    issue_stage(1, 1);

    for (int c = 0; c < NCHUNK; c++) {
        if (c < NCHUNK - 2) CP_WAIT1(); else CP_WAIT0();
        __syncthreads();
        if (c + 2 < NCHUNK) issue_stage((c + 2) % NSTAGE, c + 2);

        const uint32_t base = buf + (uint32_t)(c % NSTAGE) * STAGE_BYTES;
        const uint32_t aH = base, aL = base + 16384u, bH = base + 32768u, bL = base + 49152u;
#pragma unroll
        for (int ks = 0; ks < 4; ks++) {
            const uint32_t acol = (uint32_t)(ks * 32) + a_sel;
            const uint32_t bkrow = (uint32_t)(ks * 16) + b_rowoff;
            uint32_t ah[4][4], bh[2][4], bl[2][4];
#pragma unroll
            for (int mt = 0; mt < 4; mt++)
                LDSM4(ah[mt], aH + (a_lrow + (uint32_t)mt * 16u) * 128u + (acol ^ a_lxm));
#pragma unroll
            for (int p = 0; p < 2; p++) {
                const uint32_t boff = bkrow * 256u + (((b_colbase + (uint32_t)p * 2) ^ b_r) * 16u);
                LDSM4T(bh[p], bH + boff);
                LDSM4T(bl[p], bL + boff);
            }
#pragma unroll
            for (int mt = 0; mt < 4; mt++)
#pragma unroll
                for (int nt = 0; nt < 4; nt++) {
                    const uint32_t* bp = &bh[nt >> 1][(nt & 1) * 2];
                    MMA16816(acc[mt][nt], ah[mt], bp[0], bp[1]);
                    const uint32_t* bq = &bl[nt >> 1][(nt & 1) * 2];
                    MMA16816(acc[mt][nt], ah[mt], bq[0], bq[1]);
                }
            uint32_t al[4][4];
#pragma unroll
            for (int mt = 0; mt < 4; mt++)
                LDSM4(al[mt], aL + (a_lrow + (uint32_t)mt * 16u) * 128u + (acol ^ a_lxm));
#pragma unroll
            for (int mt = 0; mt < 4; mt++)
#pragma unroll
                for (int nt = 0; nt < 4; nt++) {
                    const uint32_t* bp = &bh[nt >> 1][(nt & 1) * 2];
                    MMA16816(acc[mt][nt], al[mt], bp[0], bp[1]);
                }
        }
    }

    // ---- epilogue ----
    const float* brow = bias + (size_t)e * 1024 + n0;
    const int ccol = warp_n * 32 + (lane & 3) * 2;
    const int crow = m0 + warp_m * 64 + (lane >> 2);
    float bv[8];
#pragma unroll
    for (int nt = 0; nt < 4; nt++) {
        bv[nt * 2 + 0] = __ldg(brow + ccol + nt * 8);
        bv[nt * 2 + 1] = __ldg(brow + ccol + nt * 8 + 1);
    }

#pragma unroll
    for (int mt = 0; mt < 4; mt++) {
#pragma unroll
        for (int half = 0; half < 2; half++) {
            const int r = crow + mt * 16 + half * 8;
            if (r >= cnt) continue;
            if (LAYER == 0) {
                const size_t idx = ((size_t)e * CAPCT + r) * 1024 + n0 + ccol;
#pragma unroll
                for (int nt = 0; nt < 4; nt++) {
                    float v0 = fmaxf(acc[mt][nt][half * 2 + 0] + bv[nt * 2 + 0], 0.f);
                    float v1 = fmaxf(acc[mt][nt][half * 2 + 1] + bv[nt * 2 + 1], 0.f);
                    __nv_bfloat162 hv, lv;
                    hv.x = __float2bfloat16(v0); hv.y = __float2bfloat16(v1);
                    lv.x = __float2bfloat16(v0 - __bfloat162float(hv.x));
                    lv.y = __float2bfloat16(v1 - __bfloat162float(hv.y));
                    *reinterpret_cast<__nv_bfloat162*>(g_h_hi + idx + nt * 8) = hv;
                    *reinterpret_cast<__nv_bfloat162*>(g_h_lo + idx + nt * 8) = lv;
                }
            } else {
                const int slot = e * CAPCT + r;
                const int tok = g_slot_tok[slot];
                const float sc = g_slot_score[slot];
                float* orow = out + (size_t)tok * 1024 + n0 + ccol;
#pragma unroll
                for (int nt = 0; nt < 4; nt++) {
                    atomicAdd(orow + nt * 8,     sc * (acc[mt][nt][half * 2 + 0] + bv[nt * 2 + 0]));
                    atomicAdd(orow + nt * 8 + 1, sc * (acc[mt][nt][half * 2 + 1] + bv[nt * 2 + 1]));
                }
            }
        }
    }
}

// ---------------- launch -----------------------------------------------------
extern "C" void kernel_launch(void* const* d_in, const int* in_sizes, int n_in,
                              void* d_out, int out_size) {
    const float* x  = (const float*)d_in[0];
    const float* Wg = (const float*)d_in[1];
    const float* bg = (const float*)d_in[2];
    const float* W1 = (const float*)d_in[3];
    const float* b1 = (const float*)d_in[4];
    const float* W2 = (const float*)d_in[5];
    const float* b2 = (const float*)d_in[6];
    float* out = (float*)d_out;

    const int SMEM_BYTES = 1024 + NSTAGE * STAGE_BYTES;   // 197632
    cudaFuncSetAttribute(gemm_tc<0>, cudaFuncAttributeMaxDynamicSharedMemorySize, SMEM_BYTES);
    cudaFuncSetAttribute(gemm_tc<1>, cudaFuncAttributeMaxDynamicSharedMemorySize, SMEM_BYTES);

    init_zero<<<(NX4 + 255) / 256, 256>>>(out);
    gate_kernel<<<T_TOK / 4, 128>>>(x, Wg, bg);
    split_all<<<(NX4 + 2 * NW4 + 255) / 256, 256>>>(x, W1, W2);

    dim3 grid(CAPCT / BM, H_DIM / BN, E_NUM);   // x = m-tile (fast), y = n-tile, z = expert
    gemm_tc<0><<<grid, 256, SMEM_BYTES>>>(b1, nullptr);
    gemm_tc<1><<<grid, 256, SMEM_BYTES>>>(b2, out);
}

// round 9
// speedup vs baseline: 1.8905x; 1.0009x over previous
#include <cuda_runtime.h>
#include <cuda_bf16.h>
#include <cstdint>

// Problem constants
#define T_TOK 4096
#define D_DIM 1024
#define H_DIM 1024
#define E_NUM 16
#define K_TOP 2
#define CAPCT 1024

// GEMM tiling
#define BM 128
#define BN 128
#define KC 64                  // K elems per chunk
#define NCHUNK (D_DIM / KC)    // 16
#define NSTAGE 3
#define STAGE_BYTES 65536      // A_hi 16K + A_lo 16K + B_hi 16K + B_lo 16K

#define NX4 ((T_TOK * D_DIM) / 4)
#define NW4 ((E_NUM * D_DIM * H_DIM) / 4)

// ---------------- scratch (device globals; no allocations allowed) ----------
__device__ int   g_count[E_NUM];
__device__ int   g_slot_tok[E_NUM * CAPCT];
__device__ float g_slot_score[E_NUM * CAPCT];

__device__ __nv_bfloat16 g_x_hi[(size_t)T_TOK * D_DIM];
__device__ __nv_bfloat16 g_x_lo[(size_t)T_TOK * D_DIM];
__device__ __nv_bfloat16 g_w1_hi[(size_t)E_NUM * D_DIM * H_DIM];
__device__ __nv_bfloat16 g_w1_lo[(size_t)E_NUM * D_DIM * H_DIM];
__device__ __nv_bfloat16 g_w2_hi[(size_t)E_NUM * H_DIM * D_DIM];
__device__ __nv_bfloat16 g_w2_lo[(size_t)E_NUM * H_DIM * D_DIM];
__device__ __nv_bfloat16 g_h_hi[(size_t)E_NUM * CAPCT * H_DIM];
__device__ __nv_bfloat16 g_h_lo[(size_t)E_NUM * CAPCT * H_DIM];

// ---------------- asm helpers ------------------------------------------------
__device__ __forceinline__ uint32_t smem_u32(const void* p) {
    uint32_t a;
    asm("{ .reg .u64 t; cvta.to.shared.u64 t, %1; cvt.u32.u64 %0, t; }" : "=r"(a) : "l"(p));
    return a;
}
#define CP16(dst, src) \
    asm volatile("cp.async.cg.shared.global [%0], [%1], 16;" :: "r"(dst), "l"(src) : "memory")
#define CP_COMMIT() asm volatile("cp.async.commit_group;" ::: "memory")
#define CP_WAIT1()  asm volatile("cp.async.wait_group 1;" ::: "memory")
#define CP_WAIT0()  asm volatile("cp.async.wait_group 0;" ::: "memory")

#define LDSM4(r, a) \
    asm volatile("ldmatrix.sync.aligned.m8n8.x4.shared.b16 {%0,%1,%2,%3}, [%4];" \
        : "=r"((r)[0]), "=r"((r)[1]), "=r"((r)[2]), "=r"((r)[3]) : "r"(a))
#define LDSM4T(r, a) \
    asm volatile("ldmatrix.sync.aligned.m8n8.x4.trans.shared.b16 {%0,%1,%2,%3}, [%4];" \
        : "=r"((r)[0]), "=r"((r)[1]), "=r"((r)[2]), "=r"((r)[3]) : "r"(a))

#define MMA16816(c, a, b0, b1) \
    asm volatile("mma.sync.aligned.m16n8k16.row.col.f32.bf16.bf16.f32 " \
        "{%0,%1,%2,%3}, {%4,%5,%6,%7}, {%8,%9}, {%0,%1,%2,%3};" \
        : "+f"((c)[0]), "+f"((c)[1]), "+f"((c)[2]), "+f"((c)[3]) \
        : "r"((a)[0]), "r"((a)[1]), "r"((a)[2]), "r"((a)[3]), "r"(b0), "r"(b1))

// split fp32x4 -> packed hi/lo bf16x4 (u64 each)
__device__ __forceinline__ void split4(float4 v, unsigned long long& hi, unsigned long long& lo) {
    __nv_bfloat16 h0 = __float2bfloat16(v.x), h1 = __float2bfloat16(v.y);
    __nv_bfloat16 h2 = __float2bfloat16(v.z), h3 = __float2bfloat16(v.w);
    __nv_bfloat16 l0 = __float2bfloat16(v.x - __bfloat162float(h0));
    __nv_bfloat16 l1 = __float2bfloat16(v.y - __bfloat162float(h1));
    __nv_bfloat16 l2 = __float2bfloat16(v.z - __bfloat162float(h2));
    __nv_bfloat16 l3 = __float2bfloat16(v.w - __bfloat162float(h3));
    hi = (unsigned long long)__bfloat16_as_ushort(h0)
       | ((unsigned long long)__bfloat16_as_ushort(h1) << 16)
       | ((unsigned long long)__bfloat16_as_ushort(h2) << 32)
       | ((unsigned long long)__bfloat16_as_ushort(h3) << 48);
    lo = (unsigned long long)__bfloat16_as_ushort(l0)
       | ((unsigned long long)__bfloat16_as_ushort(l1) << 16)
       | ((unsigned long long)__bfloat16_as_ushort(l2) << 32)
       | ((unsigned long long)__bfloat16_as_ushort(l3) << 48);
}

// ---------------- init: zero counters + output -------------------------------
__global__ void init_zero(float* __restrict__ out) {
    const size_t i = (size_t)blockIdx.x * blockDim.x + threadIdx.x;
    if (i < NX4) reinterpret_cast<float4*>(out)[i] = make_float4(0.f, 0.f, 0.f, 0.f);
    if (blockIdx.x == 0 && threadIdx.x < E_NUM) g_count[threadIdx.x] = 0;
}

// ---------------- split all three fp32 tensors -> bf16 hi/lo -----------------
__global__ void split_all(const float* __restrict__ x,
                          const float* __restrict__ W1,
                          const float* __restrict__ W2) {
    const size_t i = (size_t)blockIdx.x * blockDim.x + threadIdx.x;
    const float4* src;
    unsigned long long *hi, *lo;
    size_t off;
    if (i < NX4) {
        src = reinterpret_cast<const float4*>(x);
        hi = reinterpret_cast<unsigned long long*>(g_x_hi);
        lo = reinterpret_cast<unsigned long long*>(g_x_lo);
        off = i;
    } else if (i < NX4 + NW4) {
        src = reinterpret_cast<const float4*>(W1);
        hi = reinterpret_cast<unsigned long long*>(g_w1_hi);
        lo = reinterpret_cast<unsigned long long*>(g_w1_lo);
        off = i - NX4;
    } else if (i < NX4 + 2 * NW4) {
        src = reinterpret_cast<const float4*>(W2);
        hi = reinterpret_cast<unsigned long long*>(g_w2_hi);
        lo = reinterpret_cast<unsigned long long*>(g_w2_lo);
        off = i - NX4 - NW4;
    } else {
        return;
    }
    float4 v = __ldcs(src + off);
    unsigned long long h, l;
    split4(v, h, l);
    __stcs(hi + off, h);
    __stcs(lo + off, l);
}

// ---------------- gate: one warp per token ----------------------------------
__global__ void gate_kernel(const float* __restrict__ x,
                            const float* __restrict__ Wg,
                            const float* __restrict__ bg) {
    int warp = (blockIdx.x * blockDim.x + threadIdx.x) >> 5;
    int lane = threadIdx.x & 31;
    if (warp >= T_TOK) return;
    const float* xr = x + (size_t)warp * D_DIM;

    float acc[E_NUM];
#pragma unroll
    for (int e = 0; e < E_NUM; e++) acc[e] = 0.f;

    for (int d = lane; d < D_DIM; d += 32) {
        float xv = __ldg(xr + d);
        const float4* w = reinterpret_cast<const float4*>(Wg + (size_t)d * E_NUM);
#pragma unroll
        for (int q = 0; q < 4; q++) {
            float4 wv = __ldg(w + q);
            acc[q * 4 + 0] += xv * wv.x;
            acc[q * 4 + 1] += xv * wv.y;
            acc[q * 4 + 2] += xv * wv.z;
            acc[q * 4 + 3] += xv * wv.w;
        }
    }
#pragma unroll
    for (int e = 0; e < E_NUM; e++) {
#pragma unroll
        for (int off = 16; off > 0; off >>= 1)
            acc[e] += __shfl_xor_sync(0xffffffffu, acc[e], off);
    }

    if (lane == 0) {
        float v[E_NUM];
#pragma unroll
        for (int e = 0; e < E_NUM; e++) v[e] = acc[e] + bg[e];
        int i0 = 0; float v0 = v[0];
#pragma unroll
        for (int e = 1; e < E_NUM; e++) if (v[e] > v0) { v0 = v[e]; i0 = e; }
        int i1 = -1; float v1 = -3.4e38f;
#pragma unroll
        for (int e = 0; e < E_NUM; e++)
            if (e != i0 && v[e] > v1) { v1 = v[e]; i1 = e; }
        float e1 = expf(v1 - v0);
        float s0 = 1.f / (1.f + e1);
        float s1 = e1 / (1.f + e1);

        int p0 = atomicAdd(&g_count[i0], 1);
        int p1 = atomicAdd(&g_count[i1], 1);
        if (p0 < CAPCT) {
            g_slot_tok[i0 * CAPCT + p0] = warp;
            g_slot_score[i0 * CAPCT + p0] = s0;
        }
        if (p1 < CAPCT) {
            g_slot_tok[i1 * CAPCT + p1] = warp;
            g_slot_score[i1 * CAPCT + p1] = s1;
        }
    }
}

// ---------------- HMMA grouped GEMM (pre-split bf16, cp.async pipeline) ------
// LAYER 0: h(bf16 hi/lo) = relu( gather(x_hi/lo) @ W1 + b1 )
// LAYER 1: out[tok] += score * ( h @ W2 + b2 )   (atomic combine)
template <int LAYER>
__global__ __launch_bounds__(256, 1)
void gemm_tc(const float* __restrict__ bias, float* __restrict__ out)
{
    const int e = blockIdx.z;
    int cnt = g_count[e];
    if (cnt > CAPCT) cnt = CAPCT;
    const int m0 = blockIdx.x * BM;       // x = m-tile: consecutive CTAs share W slab
    if (m0 >= cnt) return;
    const int n0 = blockIdx.y * BN;

    extern __shared__ char smem[];
    const uint32_t buf = (smem_u32(smem) + 1023) & ~1023u;

    const int tid = threadIdx.x;
    const int lane = tid & 31;
    const int wid = tid >> 5;
    const int warp_m = wid >> 2;   // 0..1
    const int warp_n = wid & 3;    // 0..3

    const __nv_bfloat16* Whi = (LAYER == 0) ? g_w1_hi : g_w2_hi;
    const __nv_bfloat16* Wlo = (LAYER == 0) ? g_w1_lo : g_w2_lo;

    // ---- cp.async producer mappings ----
    const int arow = tid >> 1;
    const int aseg0 = (tid & 1) * 4;
    const char* a_hi_row;
    const char* a_lo_row;
    if (LAYER == 0) {
        int tok = g_slot_tok[e * CAPCT + m0 + arow];   // rows >= cnt: stale but finite
        tok = min(max(tok, 0), T_TOK - 1);
        a_hi_row = (const char*)(g_x_hi + (size_t)tok * D_DIM);
        a_lo_row = (const char*)(g_x_lo + (size_t)tok * D_DIM);
    } else {
        a_hi_row = (const char*)(g_h_hi + ((size_t)e * CAPCT + m0 + arow) * H_DIM);
        a_lo_row = (const char*)(g_h_lo + ((size_t)e * CAPCT + m0 + arow) * H_DIM);
    }
    uint32_t a_dst[4];
#pragma unroll
    for (int i = 0; i < 4; i++)
        a_dst[i] = (uint32_t)arow * 128u + ((uint32_t)((aseg0 + i) * 16) ^ ((uint32_t)(arow & 7) * 16u));

    const int krow = tid >> 2;
    const int bseg0 = (tid & 3) * 4;
    const char* b_hi_row = (const char*)(Whi + (size_t)e * (D_DIM * H_DIM) + (size_t)krow * H_DIM + n0);
    const char* b_lo_row = (const char*)(Wlo + (size_t)e * (D_DIM * H_DIM) + (size_t)krow * H_DIM + n0);
    uint32_t b_dst[4];
#pragma unroll
    for (int i = 0; i < 4; i++)
        b_dst[i] = (uint32_t)krow * 256u + ((uint32_t)((bseg0 + i) ^ (krow & 7)) * 16u);

    // ---- consumer lane addressing ----
    const uint32_t a_lrow = (uint32_t)(warp_m * 64 + (lane & 7) + ((lane >> 3) & 1) * 8);
    const uint32_t a_sel = (uint32_t)(lane >> 4) * 16u;
    const uint32_t a_lxm = (uint32_t)(lane & 7) * 16u;
    const uint32_t b_m = (uint32_t)(lane >> 3);
    const uint32_t b_r = (uint32_t)(lane & 7);
    const uint32_t b_rowoff = (b_m & 1) * 8 + b_r;
    const uint32_t b_colbase = (uint32_t)warp_n * 4 + (b_m >> 1);

    float acc[4][4][4];
#pragma unroll
    for (int mt = 0; mt < 4; mt++)
#pragma unroll
        for (int nt = 0; nt < 4; nt++)
#pragma unroll
            for (int j = 0; j < 4; j++) acc[mt][nt][j] = 0.f;

    auto issue_stage = [&](int s, int c) {
        const uint32_t sb = buf + (uint32_t)s * STAGE_BYTES;
        const size_t akb = (size_t)(c * KC) * 2;
        const size_t bkb = (size_t)(c * KC) * (H_DIM * 2);
#pragma unroll
        for (int i = 0; i < 4; i++) {
            CP16(sb + a_dst[i],          a_hi_row + akb + (aseg0 + i) * 16);
            CP16(sb + 16384u + a_dst[i], a_lo_row + akb + (aseg0 + i) * 16);
        }
#pragma unroll
        for (int i = 0; i < 4; i++) {
            CP16(sb + 32768u + b_dst[i], b_hi_row + bkb + (bseg0 + i) * 16);
            CP16(sb + 49152u + b_dst[i], b_lo_row + bkb + (bseg0 + i) * 16);
        }
        CP_COMMIT();
    };

    issue_stage(0, 0);
    issue_stage(1, 1);

    for (int c = 0; c < NCHUNK; c++) {
        if (c < NCHUNK - 2) CP_WAIT1(); else CP_WAIT0();
        __syncthreads();
        if (c + 2 < NCHUNK) issue_stage((c + 2) % NSTAGE, c + 2);

        const uint32_t base = buf + (uint32_t)(c % NSTAGE) * STAGE_BYTES;
        const uint32_t aH = base, aL = base + 16384u, bH = base + 32768u, bL = base + 49152u;
#pragma unroll
        for (int ks = 0; ks < 4; ks++) {
            const uint32_t acol = (uint32_t)(ks * 32) + a_sel;
            const uint32_t bkrow = (uint32_t)(ks * 16) + b_rowoff;
            uint32_t ah[4][4], bh[2][4], bl[2][4];
#pragma unroll
            for (int mt = 0; mt < 4; mt++)
                LDSM4(ah[mt], aH + (a_lrow + (uint32_t)mt * 16u) * 128u + (acol ^ a_lxm));
#pragma unroll
            for (int p = 0; p < 2; p++) {
                const uint32_t boff = bkrow * 256u + (((b_colbase + (uint32_t)p * 2) ^ b_r) * 16u);
                LDSM4T(bh[p], bH + boff);
                LDSM4T(bl[p], bL + boff);
            }
#pragma unroll
            for (int mt = 0; mt < 4; mt++)
#pragma unroll
                for (int nt = 0; nt < 4; nt++) {
                    const uint32_t* bp = &bh[nt >> 1][(nt & 1) * 2];
                    MMA16816(acc[mt][nt], ah[mt], bp[0], bp[1]);
                    const uint32_t* bq = &bl[nt >> 1][(nt & 1) * 2];
                    MMA16816(acc[mt][nt], ah[mt], bq[0], bq[1]);
                }
            uint32_t al[4][4];
#pragma unroll
            for (int mt = 0; mt < 4; mt++)
                LDSM4(al[mt], aL + (a_lrow + (uint32_t)mt * 16u) * 128u + (acol ^ a_lxm));
#pragma unroll
            for (int mt = 0; mt < 4; mt++)
#pragma unroll
                for (int nt = 0; nt < 4; nt++) {
                    const uint32_t* bp = &bh[nt >> 1][(nt & 1) * 2];
                    MMA16816(acc[mt][nt], al[mt], bp[0], bp[1]);
                }
        }
    }

    // ---- epilogue ----
    const float* brow = bias + (size_t)e * 1024 + n0;
    const int ccol = warp_n * 32 + (lane & 3) * 2;
    const int crow = m0 + warp_m * 64 + (lane >> 2);
    float bv[8];
#pragma unroll
    for (int nt = 0; nt < 4; nt++) {
        bv[nt * 2 + 0] = __ldg(brow + ccol + nt * 8);
        bv[nt * 2 + 1] = __ldg(brow + ccol + nt * 8 + 1);
    }

#pragma unroll
    for (int mt = 0; mt < 4; mt++) {
#pragma unroll
        for (int half = 0; half < 2; half++) {
            const int r = crow + mt * 16 + half * 8;
            if (r >= cnt) continue;
            if (LAYER == 0) {
                const size_t idx = ((size_t)e * CAPCT + r) * 1024 + n0 + ccol;
#pragma unroll
                for (int nt = 0; nt < 4; nt++) {
                    float v0 = fmaxf(acc[mt][nt][half * 2 + 0] + bv[nt * 2 + 0], 0.f);
                    float v1 = fmaxf(acc[mt][nt][half * 2 + 1] + bv[nt * 2 + 1], 0.f);
                    __nv_bfloat162 hv, lv;
                    hv.x = __float2bfloat16(v0); hv.y = __float2bfloat16(v1);
                    lv.x = __float2bfloat16(v0 - __bfloat162float(hv.x));
                    lv.y = __float2bfloat16(v1 - __bfloat162float(hv.y));
                    *reinterpret_cast<__nv_bfloat162*>(g_h_hi + idx + nt * 8) = hv;
                    *reinterpret_cast<__nv_bfloat162*>(g_h_lo + idx + nt * 8) = lv;
                }
            } else {
                const int slot = e * CAPCT + r;
                const int tok = g_slot_tok[slot];
                const float sc = g_slot_score[slot];
                float* orow = out + (size_t)tok * 1024 + n0 + ccol;
#pragma unroll
                for (int nt = 0; nt < 4; nt++) {
                    atomicAdd(orow + nt * 8,     sc * (acc[mt][nt][half * 2 + 0] + bv[nt * 2 + 0]));
                    atomicAdd(orow + nt * 8 + 1, sc * (acc[mt][nt][half * 2 + 1] + bv[nt * 2 + 1]));
                }
            }
        }
    }
}

// ---------------- launch -----------------------------------------------------
extern "C" void kernel_launch(void* const* d_in, const int* in_sizes, int n_in,
                              void* d_out, int out_size) {
    const float* x  = (const float*)d_in[0];
    const float* Wg = (const float*)d_in[1];
    const float* bg = (const float*)d_in[2];
    const float* W1 = (const float*)d_in[3];
    const float* b1 = (const float*)d_in[4];
    const float* W2 = (const float*)d_in[5];
    const float* b2 = (const float*)d_in[6];
    float* out = (float*)d_out;

    const int SMEM_BYTES = 1024 + NSTAGE * STAGE_BYTES;   // 197632
    cudaFuncSetAttribute(gemm_tc<0>, cudaFuncAttributeMaxDynamicSharedMemorySize, SMEM_BYTES);
    cudaFuncSetAttribute(gemm_tc<1>, cudaFuncAttributeMaxDynamicSharedMemorySize, SMEM_BYTES);

    init_zero<<<(NX4 + 255) / 256, 256>>>(out);
    gate_kernel<<<T_TOK / 4, 128>>>(x, Wg, bg);
    split_all<<<(NX4 + 2 * NW4 + 255) / 256, 256>>>(x, W1, W2);

    dim3 grid(CAPCT / BM, H_DIM / BN, E_NUM);   // x = m-tile (fast), y = n-tile, z = expert
    gemm_tc<0><<<grid, 256, SMEM_BYTES>>>(b1, nullptr);
    gemm_tc<1><<<grid, 256, SMEM_BYTES>>>(b2, out);
}